// round 5
// baseline (speedup 1.0000x reference)
#include <cuda_runtime.h>

constexpr int N     = 128;
constexpr int MAXIT = 8;

// Two problems per CTA. All per-problem vectors interleaved {p0,p1}.
struct SM {
    __align__(16) float d2 [2 * N];
    __align__(16) float g2 [2 * N];
    __align__(16) float s2 [2 * N];
    __align__(16) float dg2[2 * N];
    __align__(16) float hy2[2 * N];
    __align__(16) float2 qp[512];     // per-thread partial dots
    __align__(16) float red[64];      // 16 warps x 4 values
};

__device__ __forceinline__ float warp_sum(float v) {
    #pragma unroll
    for (int o = 16; o > 0; o >>= 1) v += __shfl_xor_sync(0xffffffffu, v, o);
    return v;
}

// four simultaneous block reductions over 512 threads (16 warps)
__device__ __forceinline__ void block_sum4(float& a, float& b, float& c, float& d,
                                           float* red, int t) {
    a = warp_sum(a); b = warp_sum(b); c = warp_sum(c); d = warp_sum(d);
    const int w = t >> 5;
    if ((t & 31) == 0) { red[w] = a; red[16 + w] = b; red[32 + w] = c; red[48 + w] = d; }
    __syncthreads();
    const float4* r4 = reinterpret_cast<const float4*>(red);
    float4 A = make_float4(0.f, 0.f, 0.f, 0.f);
    float4 B = A, C = A, D = A;
    #pragma unroll
    for (int k = 0; k < 4; k++) {
        float4 x = r4[k], y = r4[4 + k], z = r4[8 + k], w4 = r4[12 + k];
        A.x += x.x; A.y += x.y; A.z += x.z; A.w += x.w;
        B.x += y.x; B.y += y.y; B.z += y.z; B.w += y.w;
        C.x += z.x; C.y += z.y; C.z += z.z; C.w += z.w;
        D.x += w4.x; D.y += w4.y; D.z += w4.z; D.w += w4.w;
    }
    a = (A.x + A.y) + (A.z + A.w);
    b = (B.x + B.y) + (B.z + B.w);
    c = (C.x + C.y) + (C.z + C.w);
    d = (D.x + D.y) + (D.z + D.w);
    __syncthreads();
}

__global__ __launch_bounds__(512, 1)
void bfgs_kernel(const float* __restrict__ Hinit,
                 const float* __restrict__ Q,
                 const float* __restrict__ bvec,
                 const float* __restrict__ x0,
                 float* __restrict__ out)
{
    __shared__ SM sm;

    const int t     = threadIdx.x;
    const int i     = t & 127;          // row / vector element
    const int q     = t >> 7;           // column-chunk quarter 0..3
    const int kbase = q * 32;
    const int p0    = 2 * blockIdx.x;
    const int p1    = p0 + 1;

    const float* qcol = Q + (size_t)kbase * N + i;   // Q[(kbase+k)*N + i]

    // ---- H chunk -> registers, interleaved {p0,p1} per column ----
    float4 hr[16];
    {
        const float2* hin = reinterpret_cast<const float2*>(Hinit + i * N + kbase);
        #pragma unroll
        for (int j = 0; j < 16; j++) {
            float2 w = hin[j];
            hr[j] = make_float4(w.x, w.x, w.y, w.y);   // same init both problems
        }
    }

    float2 x2r = make_float2(0.f, 0.f), g2r = x2r, d2r = x2r;
    if (q == 0) {
        x2r = make_float2(x0[p0 * N + i], x0[p1 * N + i]);
        reinterpret_cast<float2*>(sm.d2)[i] = x2r;     // stage x in d slot
    }
    __syncthreads();

    // ---- g0 = Q x0 - b (both problems share each Q load) ----
    {
        float a0 = 0.f, a1 = 0.f;
        const float4* dv = reinterpret_cast<const float4*>(sm.d2 + 2 * kbase);
        #pragma unroll
        for (int j = 0; j < 16; j++) {
            float qv0 = qcol[(2 * j) * N], qv1 = qcol[(2 * j + 1) * N];
            float4 v = dv[j];
            a0 += qv0 * v.x + qv1 * v.z;
            a1 += qv0 * v.y + qv1 * v.w;
        }
        sm.qp[t] = make_float2(a0, a1);
    }
    __syncthreads();
    if (q == 0) {
        float2 a = sm.qp[i], b = sm.qp[128 + i], c = sm.qp[256 + i], d = sm.qp[384 + i];
        g2r.x = (a.x + b.x) + (c.x + d.x) - bvec[p0 * N + i];
        g2r.y = (a.y + b.y) + (c.y + d.y) - bvec[p1 * N + i];
        reinterpret_cast<float2*>(sm.g2)[i] = g2r;
    }
    __syncthreads();

    // ---- d0 = -H g0 ----
    {
        float a0 = 0.f, a1 = 0.f;
        const float4* gv = reinterpret_cast<const float4*>(sm.g2 + 2 * kbase);
        #pragma unroll
        for (int j = 0; j < 16; j++) {
            float4 v = gv[j];
            a0 += hr[j].x * v.x + hr[j].z * v.z;
            a1 += hr[j].y * v.y + hr[j].w * v.w;
        }
        sm.qp[t] = make_float2(a0, a1);
    }
    __syncthreads();
    if (q == 0) {
        float2 a = sm.qp[i], b = sm.qp[128 + i], c = sm.qp[256 + i], d = sm.qp[384 + i];
        d2r = make_float2(-((a.x + b.x) + (c.x + d.x)), -((a.y + b.y) + (c.y + d.y)));
        reinterpret_cast<float2*>(sm.d2)[i] = d2r;
    }
    __syncthreads();

    bool m0 = true, m1 = true;   // per-problem "updating" flags (block-uniform)

    for (int it = 0; it < MAXIT; ++it) {
        // ---- qd = Q d, one Q load feeds both problems ----
        float qdp0 = 0.f, qdp1 = 0.f;
        {
            const float4* dv = reinterpret_cast<const float4*>(sm.d2 + 2 * kbase);
            #pragma unroll
            for (int j = 0; j < 16; j++) {
                float qv0 = qcol[(2 * j) * N], qv1 = qcol[(2 * j + 1) * N];
                float4 v = dv[j];
                qdp0 += qv0 * v.x + qv1 * v.z;
                qdp1 += qv0 * v.y + qv1 * v.w;
            }
            sm.qp[t] = make_float2(qdp0, qdp1);
        }
        float2 dd = reinterpret_cast<const float2*>(sm.d2)[i];
        float dq0 = dd.x * qdp0, dq1 = dd.y * qdp1;           // -> d.Qd
        float gd0 = (q == 0) ? g2r.x * d2r.x : 0.f;           // -> g.d (owners only)
        float gd1 = (q == 0) ? g2r.y * d2r.y : 0.f;
        block_sum4(gd0, gd1, dq0, dq1, sm.red, t);            // syncs publish qp

        const float al0  = -gd0 / fmaxf(dq0, 1e-12f);
        const float al1  = -gd1 / fmaxf(dq1, 1e-12f);
        const float sdg0 = al0 * al0 * dq0;                   // s.dg = a^2 d.Qd
        const float sdg1 = al1 * al1 * dq1;

        float2 gn2 = make_float2(0.f, 0.f), s2r = gn2;
        if (q == 0) {
            float2 a = sm.qp[i], b = sm.qp[128 + i], c = sm.qp[256 + i], d = sm.qp[384 + i];
            float qd0 = (a.x + b.x) + (c.x + d.x);
            float qd1 = (a.y + b.y) + (c.y + d.y);
            float dg0 = al0 * qd0, dg1 = al1 * qd1;           // dg = a*Qd (quadratic)
            gn2 = make_float2(g2r.x + dg0, g2r.y + dg1);
            s2r = make_float2(al0 * d2r.x, al1 * d2r.y);
            reinterpret_cast<float2*>(sm.dg2)[i] = make_float2(dg0, dg1);
            reinterpret_cast<float2*>(sm.s2)[i]  = s2r;
        }
        __syncthreads();

        // ---- Hy = H dg (register H) ----
        {
            float a0 = 0.f, a1 = 0.f;
            const float4* yv = reinterpret_cast<const float4*>(sm.dg2 + 2 * kbase);
            #pragma unroll
            for (int j = 0; j < 16; j++) {
                float4 v = yv[j];
                a0 += hr[j].x * v.x + hr[j].z * v.z;
                a1 += hr[j].y * v.y + hr[j].w * v.w;
            }
            sm.qp[t] = make_float2(a0, a1);
        }
        __syncthreads();

        float ih0 = 0.f, ih1 = 0.f, e0 = 0.f, e1 = 0.f;
        if (q == 0) {
            float2 a = sm.qp[i], b = sm.qp[128 + i], c = sm.qp[256 + i], d = sm.qp[384 + i];
            float hy0 = (a.x + b.x) + (c.x + d.x);
            float hy1 = (a.y + b.y) + (c.y + d.y);
            reinterpret_cast<float2*>(sm.hy2)[i] = make_float2(hy0, hy1);
            float2 dgv = reinterpret_cast<const float2*>(sm.dg2)[i];
            ih0 = dgv.x * hy0; ih1 = dgv.y * hy1;             // -> ihdg
            // commit x,g with OLD mask
            g2r = make_float2(m0 ? gn2.x : g2r.x, m1 ? gn2.y : g2r.y);
            x2r = make_float2(m0 ? x2r.x + s2r.x : x2r.x, m1 ? x2r.y + s2r.y : x2r.y);
            reinterpret_cast<float2*>(sm.g2)[i] = g2r;
            e0 = g2r.x * g2r.x; e1 = g2r.y * g2r.y;           // -> ||g||^2
        }
        block_sum4(ih0, ih1, e0, e1, sm.red, t);              // publishes hy2, g2

        // ---- BFGS coefficients (sdg == 0 -> dH = 0, as reference) ----
        const bool  nz0 = (sdg0 != 0.f), nz1 = (sdg1 != 0.f);
        const float bi0 = nz0 ? 1.f / sdg0 : 0.f;
        const float bi1 = nz1 ? 1.f / sdg1 : 0.f;
        const float c10 = nz0 ? (sdg0 + ih0) * bi0 * bi0 : 0.f;
        const float c11 = nz1 ? (sdg1 + ih1) * bi1 * bi1 : 0.f;
        const float2 srow = reinterpret_cast<const float2*>(sm.s2)[i];
        const float2 hrow = reinterpret_cast<const float2*>(sm.hy2)[i];
        const float a0c = srow.x * c10 - bi0 * hrow.x;   // row-i coeff of s[j]
        const float b0c = bi0 * srow.x;                  // row-i coeff of Hy[j]
        const float a1c = srow.y * c11 - bi1 * hrow.y;
        const float b1c = bi1 * srow.y;

        // ---- H += a s' - b Hy' (registers), fused d_next = -H_new g ----
        {
            float dp0 = 0.f, dp1 = 0.f;
            const float4* s4 = reinterpret_cast<const float4*>(sm.s2  + 2 * kbase);
            const float4* y4 = reinterpret_cast<const float4*>(sm.hy2 + 2 * kbase);
            const float4* g4 = reinterpret_cast<const float4*>(sm.g2  + 2 * kbase);
            #pragma unroll
            for (int j = 0; j < 16; j++) {
                float4 sv = s4[j], yv = y4[j], gv = g4[j];
                hr[j].x += a0c * sv.x - b0c * yv.x;  dp0 += hr[j].x * gv.x;
                hr[j].y += a1c * sv.y - b1c * yv.y;  dp1 += hr[j].y * gv.y;
                hr[j].z += a0c * sv.z - b0c * yv.z;  dp0 += hr[j].z * gv.z;
                hr[j].w += a1c * sv.w - b1c * yv.w;  dp1 += hr[j].w * gv.w;
            }
            sm.qp[t] = make_float2(dp0, dp1);
        }
        __syncthreads();
        if (q == 0) {
            float2 a = sm.qp[i], b = sm.qp[128 + i], c = sm.qp[256 + i], d = sm.qp[384 + i];
            d2r = make_float2(-((a.x + b.x) + (c.x + d.x)),
                              -((a.y + b.y) + (c.y + d.y)));
            reinterpret_cast<float2*>(sm.d2)[i] = d2r;
        }
        m0 = m0 && (e0 > 1e-12f);   // err > 1e-6  <=>  err^2 > 1e-12
        m1 = m1 && (e1 > 1e-12f);
        __syncthreads();
    }

    if (q == 0) {
        out[p0 * N + i] = x2r.x;
        out[p1 * N + i] = x2r.y;
    }
}

extern "C" void kernel_launch(void* const* d_in, const int* in_sizes, int n_in,
                              void* d_out, int out_size)
{
    const float* Hinit = (const float*)d_in[0];
    const float* Q     = (const float*)d_in[1];
    const float* bvec  = (const float*)d_in[2];
    const float* x0    = (const float*)d_in[3];
    float*       out   = (float*)d_out;

    const int nprob = out_size / N;          // B*E = 1024 (even)
    bfgs_kernel<<<nprob / 2, 512>>>(Hinit, Q, bvec, x0, out);
}

// round 6
// speedup vs baseline: 1.0535x; 1.0535x over previous
#include <cuda_runtime.h>

constexpr int N     = 128;
constexpr int MAXIT = 8;

struct SM {
    __align__(16) float d [N];
    __align__(16) float g [N];
    __align__(16) float s [N];
    __align__(16) float dg[N];
    __align__(16) float Hy[N];
    __align__(16) float qp[2 * N];   // per-thread partials: qp[half*128 + i]
    __align__(16) float red[16];     // 8 warps x 2 values
};

__device__ __forceinline__ float warp_sum(float v) {
    #pragma unroll
    for (int o = 16; o > 0; o >>= 1) v += __shfl_xor_sync(0xffffffffu, v, o);
    return v;
}

__global__ __launch_bounds__(256, 2)
void bfgs_kernel(const float* __restrict__ Hinit,
                 const float* __restrict__ Q,
                 const float* __restrict__ bvec,
                 const float* __restrict__ x0,
                 float* __restrict__ out)
{
    __shared__ SM sm;

    const int t     = threadIdx.x;
    const int i     = t & 127;        // row / vector element owned
    const int half  = t >> 7;         // 64-column chunk of row i
    const int kbase = half * 64;
    const int w     = t >> 5;
    const int p     = blockIdx.x;

    const float* qcol = Q + (size_t)kbase * N + i;   // Q[(kbase+k)*N + i]

    // ---- H chunk -> registers (row i, cols [kbase, kbase+64)) ----
    float4 h[16];
    {
        const float4* hin = reinterpret_cast<const float4*>(Hinit + i * N + kbase);
        #pragma unroll
        for (int k = 0; k < 16; k++) h[k] = hin[k];
    }

    float g_i = 0.f, x_i = 0.f, d_i = 0.f;
    if (half == 0) {
        x_i = x0[p * N + i];
        sm.d[i] = x_i;                // stage x in d slot
    }
    __syncthreads();

    // ---- g0 = Q x0 - b ----
    {
        const float4* dv = reinterpret_cast<const float4*>(sm.d + kbase);
        float acc = 0.f;
        #pragma unroll
        for (int j = 0; j < 16; j++) {
            float4 v = dv[j];
            acc += qcol[(4 * j + 0) * N] * v.x;
            acc += qcol[(4 * j + 1) * N] * v.y;
            acc += qcol[(4 * j + 2) * N] * v.z;
            acc += qcol[(4 * j + 3) * N] * v.w;
        }
        sm.qp[t] = acc;
    }
    __syncthreads();
    if (half == 0) {
        g_i = sm.qp[i] + sm.qp[128 + i] - bvec[p * N + i];
        sm.g[i] = g_i;
    }
    __syncthreads();

    // ---- d0 = -H g0 ----
    {
        const float4* gv = reinterpret_cast<const float4*>(sm.g + kbase);
        float dp = 0.f;
        #pragma unroll
        for (int k = 0; k < 16; k++) {
            float4 v = gv[k];
            dp += h[k].x * v.x; dp += h[k].y * v.y;
            dp += h[k].z * v.z; dp += h[k].w * v.w;
        }
        sm.qp[t] = dp;
    }
    __syncthreads();
    if (half == 0) {
        d_i = -(sm.qp[i] + sm.qp[128 + i]);
        sm.d[i] = d_i;
    }
    __syncthreads();

    bool mask = true;   // block-uniform "updating" flag

    for (int it = 0; it < MAXIT; ++it) {
        // ================= Phase A: qd = Q d, alpha, s/dg =================
        float qdp = 0.f;
        {
            const float4* dv = reinterpret_cast<const float4*>(sm.d + kbase);
            #pragma unroll
            for (int j = 0; j < 16; j++) {
                float4 v = dv[j];
                qdp += qcol[(4 * j + 0) * N] * v.x;
                qdp += qcol[(4 * j + 1) * N] * v.y;
                qdp += qcol[(4 * j + 2) * N] * v.z;
                qdp += qcol[(4 * j + 3) * N] * v.w;
            }
        }
        sm.qp[t] = qdp;
        float gdp  = (half == 0) ? g_i * d_i : 0.f;   // g.d per-element (owners)
        float dqdp = sm.d[i] * qdp;                   // sum_t d_i*partial = d.Qd
        gdp  = warp_sum(gdp);
        dqdp = warp_sum(dqdp);
        if ((t & 31) == 0) { sm.red[w] = gdp; sm.red[8 + w] = dqdp; }
        __syncthreads();                              // A1: qp + red visible
        const float gd  = sm.red[0] + sm.red[1] + sm.red[2] + sm.red[3]
                        + sm.red[4] + sm.red[5] + sm.red[6] + sm.red[7];
        const float dqd = sm.red[8] + sm.red[9] + sm.red[10] + sm.red[11]
                        + sm.red[12] + sm.red[13] + sm.red[14] + sm.red[15];

        const float alpha = -gd / fmaxf(dqd, 1e-12f);
        const float sdg   = alpha * alpha * dqd;      // s.dg = a^2 d.Qd exactly

        float s_i = 0.f, gn_i = 0.f;
        if (half == 0) {
            const float qd_i = sm.qp[i] + sm.qp[128 + i];
            const float dg_i = alpha * qd_i;          // dg = a*Qd on quadratic
            gn_i = g_i + dg_i;
            s_i  = alpha * d_i;
            sm.dg[i] = dg_i;
            sm.s[i]  = s_i;
        }
        __syncthreads();                              // A2: dg, s visible

        // ========= Phase B: Hy = H dg, ihdg, err2, commit x/g =========
        float hp = 0.f;
        {
            const float4* yv = reinterpret_cast<const float4*>(sm.dg + kbase);
            #pragma unroll
            for (int k = 0; k < 16; k++) {
                float4 v = yv[k];
                hp += h[k].x * v.x; hp += h[k].y * v.y;
                hp += h[k].z * v.z; hp += h[k].w * v.w;
            }
        }
        sm.qp[t] = hp;
        // ihdg = sum_i dg_i*Hy_i = sum_t dg_row(t) * partial(t): no pre-combine
        float ihp = sm.dg[i] * hp;
        float e2p = 0.f;
        if (half == 0) {
            const float gc = mask ? gn_i : g_i;       // commit with OLD mask
            const float xc = mask ? x_i + s_i : x_i;
            g_i = gc; x_i = xc;
            sm.g[i] = gc;
            e2p = gc * gc;
        }
        ihp = warp_sum(ihp);
        e2p = warp_sum(e2p);
        if ((t & 31) == 0) { sm.red[w] = ihp; sm.red[8 + w] = e2p; }
        __syncthreads();                              // B1: qp, red, g visible
        const float ihdg = sm.red[0] + sm.red[1] + sm.red[2] + sm.red[3]
                         + sm.red[4] + sm.red[5] + sm.red[6] + sm.red[7];
        const float err2 = sm.red[8] + sm.red[9] + sm.red[10] + sm.red[11]
                         + sm.red[12] + sm.red[13] + sm.red[14] + sm.red[15];

        // every thread derives its row's Hy itself (qp visible after B1)
        const float hy_row = sm.qp[i] + sm.qp[128 + i];
        if (half == 0) sm.Hy[i] = hy_row;             // stream for update loop
        const float s_row = sm.s[i];

        const bool  nz  = (sdg != 0.0f);
        const float biv = nz ? 1.0f / sdg : 0.0f;
        const float c1  = nz ? (sdg + ihdg) * biv * biv : 0.0f;
        const float a_i = s_row * c1 - biv * hy_row;  // coeff of s[j]
        const float b_i = biv * s_row;                // coeff of Hy[j]
        __syncthreads();                              // B2: Hy visible

        // ==== Phase C: H += a s' - b Hy' (regs), fused d_next = -H g ====
        {
            const float4* s4 = reinterpret_cast<const float4*>(sm.s  + kbase);
            const float4* y4 = reinterpret_cast<const float4*>(sm.Hy + kbase);
            const float4* g4 = reinterpret_cast<const float4*>(sm.g  + kbase);
            float dp = 0.f;
            #pragma unroll
            for (int k = 0; k < 16; k++) {
                float4 sv = s4[k], yv = y4[k], gv = g4[k];
                h[k].x += a_i * sv.x - b_i * yv.x;  dp += h[k].x * gv.x;
                h[k].y += a_i * sv.y - b_i * yv.y;  dp += h[k].y * gv.y;
                h[k].z += a_i * sv.z - b_i * yv.z;  dp += h[k].z * gv.z;
                h[k].w += a_i * sv.w - b_i * yv.w;  dp += h[k].w * gv.w;
            }
            sm.qp[t] = dp;
        }
        __syncthreads();                              // C1: qp visible
        if (half == 0) {
            d_i = -(sm.qp[i] + sm.qp[128 + i]);
            sm.d[i] = d_i;
        }
        mask = mask && (err2 > 1e-12f);               // err>1e-6 <=> err^2>1e-12
        __syncthreads();                              // C2: d visible
    }

    if (half == 0) out[p * N + i] = x_i;
}

extern "C" void kernel_launch(void* const* d_in, const int* in_sizes, int n_in,
                              void* d_out, int out_size)
{
    const float* Hinit = (const float*)d_in[0];
    const float* Q     = (const float*)d_in[1];
    const float* bvec  = (const float*)d_in[2];
    const float* x0    = (const float*)d_in[3];
    float*       out   = (float*)d_out;

    const int nprob = out_size / N;   // B*E = 1024
    bfgs_kernel<<<nprob, 256>>>(Hinit, Q, bvec, x0, out);
}

// round 7
// speedup vs baseline: 1.2866x; 1.2213x over previous
#include <cuda_runtime.h>

constexpr int N     = 128;   // problem dimension
constexpr int MAXIT = 8;

// Small shared scratch: vectors + partial-combine buffer. H lives in registers.
struct SM {
    __align__(16) float d [N];
    __align__(16) float g [N];
    __align__(16) float s [N];
    __align__(16) float dg[N];
    __align__(16) float Hy[N];
    __align__(16) float qp[2 * N];   // per-thread partial dots
    __align__(16) float red[16];     // 8 warps x 2 values
};

__device__ __forceinline__ float warp_sum(float v) {
    #pragma unroll
    for (int o = 16; o > 0; o >>= 1) v += __shfl_xor_sync(0xffffffffu, v, o);
    return v;
}

// two simultaneous block reductions over 256 threads (8 warps), 2 barriers
__device__ __forceinline__ void block_sum2(float& a, float& b, float* red, int tid) {
    a = warp_sum(a); b = warp_sum(b);
    const int w = tid >> 5;
    if ((tid & 31) == 0) { red[w] = a; red[8 + w] = b; }
    __syncthreads();
    const float4* r4 = reinterpret_cast<const float4*>(red);
    float4 A = r4[0], B = r4[1], C = r4[2], D = r4[3];
    a = (A.x + A.y) + (A.z + A.w) + (B.x + B.y) + (B.z + B.w);
    b = (C.x + C.y) + (C.z + C.w) + (D.x + D.y) + (D.z + D.w);
    __syncthreads();
}

__global__ __launch_bounds__(256, 2)
void bfgs_kernel(const float* __restrict__ Hinit,
                 const float* __restrict__ Q,
                 const float* __restrict__ bvec,
                 const float* __restrict__ x0,
                 float* __restrict__ out)
{
    __shared__ SM sm;

    const int t     = threadIdx.x;
    const int i     = t & 127;        // row / vector element owned
    const int half  = t >> 7;         // which 64-column chunk of row i
    const int kbase = half * 64;
    const int p     = blockIdx.x;

    const float* bp = bvec + p * N;
    const float* qcol = Q + (size_t)kbase * N + i;   // Q[(kbase+k)*N + i] = qcol[k*N]

    // ---- H chunk -> registers (row i, cols [kbase, kbase+64)) ----
    float4 h[16];
    {
        const float4* hin = reinterpret_cast<const float4*>(Hinit + i * N + kbase);
        #pragma unroll
        for (int k = 0; k < 16; k++) h[k] = hin[k];
    }

    float x_i = 0.f, g_i = 0.f, d_i = 0.f;
    if (half == 0) {
        x_i = x0[p * N + i];
        sm.d[i] = x_i;                // stage x in d slot
    }
    __syncthreads();

    // ---- g0 = Q x0 - b (vectorized broadcast of x) ----
    {
        const float4* dv = reinterpret_cast<const float4*>(sm.d + kbase);
        float part = 0.f;
        #pragma unroll 4
        for (int j = 0; j < 16; j++) {
            float4 v = dv[j];
            part += qcol[(4 * j + 0) * N] * v.x;
            part += qcol[(4 * j + 1) * N] * v.y;
            part += qcol[(4 * j + 2) * N] * v.z;
            part += qcol[(4 * j + 3) * N] * v.w;
        }
        sm.qp[t] = part;
    }
    __syncthreads();
    if (half == 0) {
        g_i = sm.qp[i] + sm.qp[128 + i] - bp[i];
        sm.g[i] = g_i;
    }
    __syncthreads();

    // ---- d0 = -H g0 (register H, split dot) ----
    {
        const float4* gv = reinterpret_cast<const float4*>(sm.g + kbase);
        float dp = 0.f;
        #pragma unroll
        for (int k = 0; k < 16; k++) {
            float4 v = gv[k];
            dp += h[k].x * v.x; dp += h[k].y * v.y;
            dp += h[k].z * v.z; dp += h[k].w * v.w;
        }
        sm.qp[t] = dp;
    }
    __syncthreads();
    if (half == 0) {
        d_i = -(sm.qp[i] + sm.qp[128 + i]);
        sm.d[i] = d_i;
    }
    __syncthreads();

    bool mask = true;   // block-uniform "updating" flag

    for (int it = 0; it < MAXIT; ++it) {
        // ---- qd = Q d (split columns, vectorized d broadcast) ----
        float qdp = 0.f;
        {
            const float4* dv = reinterpret_cast<const float4*>(sm.d + kbase);
            #pragma unroll 4
            for (int j = 0; j < 16; j++) {
                float4 v = dv[j];
                qdp += qcol[(4 * j + 0) * N] * v.x;
                qdp += qcol[(4 * j + 1) * N] * v.y;
                qdp += qcol[(4 * j + 2) * N] * v.z;
                qdp += qcol[(4 * j + 3) * N] * v.w;
            }
        }
        sm.qp[t] = qdp;
        // g.d: per-element product, contributed ONLY by half-0 threads
        float gdp  = (half == 0) ? g_i * d_i : 0.f;
        float dqdp = sm.d[i] * qdp;          // sum_t d_i * partial = d.Qd
        block_sum2(gdp, dqdp, sm.red, t);    // syncs make qp visible
        const float gd = gdp, dqd = dqdp;

        const float alpha = -gd / fmaxf(dqd, 1e-12f);
        const float sdg   = alpha * alpha * dqd;   // s.dg = a^2 d.Qd exactly

        float s_i = 0.f, gn_i = 0.f;
        if (half == 0) {
            const float qd_i = sm.qp[i] + sm.qp[128 + i];
            const float dg_i = alpha * qd_i;       // dg = a * Qd (quadratic)
            gn_i = g_i + dg_i;
            s_i  = alpha * d_i;
            sm.dg[i] = dg_i;
            sm.s[i]  = s_i;
        }
        __syncthreads();

        // ---- Hy = H dg (register H); commit x,g with OLD mask ----
        {
            const float4* yv = reinterpret_cast<const float4*>(sm.dg + kbase);
            float hp = 0.f;
            #pragma unroll
            for (int k = 0; k < 16; k++) {
                float4 v = yv[k];
                hp += h[k].x * v.x; hp += h[k].y * v.y;
                hp += h[k].z * v.z; hp += h[k].w * v.w;
            }
            sm.qp[t] = hp;
        }
        __syncthreads();

        float ihp = 0.f, e2p = 0.f;
        if (half == 0) {
            const float hy_i = sm.qp[i] + sm.qp[128 + i];
            sm.Hy[i] = hy_i;
            ihp = sm.dg[i] * hy_i;                 // -> ihdg
            const float gc = mask ? gn_i : g_i;    // commit with old mask
            const float xc = mask ? x_i + s_i : x_i;
            g_i = gc; x_i = xc;
            sm.g[i] = gc;
            e2p = gc * gc;                         // -> ||g||^2
        }
        block_sum2(ihp, e2p, sm.red, t);           // makes Hy, g visible too
        const float ihdg = ihp, err2 = e2p;

        // ---- BFGS coefficients (sdg == 0 -> dH = 0, as reference) ----
        const bool  nz  = (sdg != 0.0f);
        const float biv = nz ? 1.0f / sdg : 0.0f;
        const float c1  = nz ? (sdg + ihdg) * biv * biv : 0.0f;
        const float s_row  = sm.s[i];
        const float hy_row = sm.Hy[i];
        const float a_i = s_row * c1 - biv * hy_row;  // coeff of s[j]
        const float b_i = biv * s_row;                // coeff of Hy[j]

        // ---- H += a_i s' - b_i Hy' in registers, fused d_next = -H_new g ----
        {
            const float4* s4 = reinterpret_cast<const float4*>(sm.s  + kbase);
            const float4* y4 = reinterpret_cast<const float4*>(sm.Hy + kbase);
            const float4* g4 = reinterpret_cast<const float4*>(sm.g  + kbase);
            float dp = 0.f;
            #pragma unroll
            for (int k = 0; k < 16; k++) {
                float4 sv = s4[k], yv = y4[k], gv = g4[k];
                h[k].x += a_i * sv.x - b_i * yv.x;  dp += h[k].x * gv.x;
                h[k].y += a_i * sv.y - b_i * yv.y;  dp += h[k].y * gv.y;
                h[k].z += a_i * sv.z - b_i * yv.z;  dp += h[k].z * gv.z;
                h[k].w += a_i * sv.w - b_i * yv.w;  dp += h[k].w * gv.w;
            }
            sm.qp[t] = dp;
        }
        __syncthreads();
        if (half == 0) {
            d_i = -(sm.qp[i] + sm.qp[128 + i]);
            sm.d[i] = d_i;
        }
        mask = mask && (err2 > 1e-12f);   // err > 1e-6  <=>  err^2 > 1e-12
        __syncthreads();
    }

    if (half == 0) out[p * N + i] = x_i;
}

extern "C" void kernel_launch(void* const* d_in, const int* in_sizes, int n_in,
                              void* d_out, int out_size)
{
    const float* Hinit = (const float*)d_in[0];
    const float* Q     = (const float*)d_in[1];
    const float* bvec  = (const float*)d_in[2];
    const float* x0    = (const float*)d_in[3];
    float*       out   = (float*)d_out;

    const int nprob = out_size / N;   // B*E = 1024
    bfgs_kernel<<<nprob, 256>>>(Hinit, Q, bvec, x0, out);
}

// round 8
// speedup vs baseline: 1.4955x; 1.1624x over previous
#include <cuda_runtime.h>

constexpr int N     = 128;
constexpr int MAXIT = 8;

struct SM {
    __align__(16) float d  [N];
    __align__(16) float g  [N];          // prologue only
    __align__(16) float dg [N];
    __align__(16) float s  [2][N];       // double-buffered (lazy update)
    __align__(16) float Hy [2][N];       // double-buffered
    __align__(16) float qp [2 * N];      // per-thread partials
    __align__(16) float red[16];         // 8 warps x 2
};

__device__ __forceinline__ float warp_sum(float v) {
    #pragma unroll
    for (int o = 16; o > 0; o >>= 1) v += __shfl_xor_sync(0xffffffffu, v, o);
    return v;
}

// two simultaneous block reductions over 256 threads (8 warps)
__device__ __forceinline__ void block_sum2(float& a, float& b, float* red, int tid) {
    a = warp_sum(a); b = warp_sum(b);
    const int w = tid >> 5;
    if ((tid & 31) == 0) { red[w] = a; red[8 + w] = b; }
    __syncthreads();
    const float4* r4 = reinterpret_cast<const float4*>(red);
    float4 A = r4[0], B = r4[1], C = r4[2], D = r4[3];
    a = (A.x + A.y) + (A.z + A.w) + (B.x + B.y) + (B.z + B.w);
    b = (C.x + C.y) + (C.z + C.w) + (D.x + D.y) + (D.z + D.w);
    __syncthreads();
}

__global__ __launch_bounds__(256, 2)
void bfgs_kernel(const float* __restrict__ Hinit,
                 const float* __restrict__ Q,
                 const float* __restrict__ bvec,
                 const float* __restrict__ x0,
                 float* __restrict__ out)
{
    __shared__ SM sm;

    const int t     = threadIdx.x;
    const int i     = t & 127;         // row / element owned
    const int half  = t >> 7;          // 64-column chunk of row i
    const int kbase = half * 64;
    const int p     = blockIdx.x;

    const float* qcol = Q + (size_t)kbase * N + i;       // Q[(kbase+k)*N + i]

    // ---- H chunk -> registers. H is symmetric, so load the TRANSPOSE:
    //      Hinit[(kbase+k)*N + i] is lane-coalesced (1 line/load vs 32). ----
    float4 h[16];
    {
        const float* hcol = Hinit + (size_t)kbase * N + i;
        #pragma unroll 4
        for (int j = 0; j < 16; j++) {
            h[j].x = hcol[(4 * j + 0) * N];
            h[j].y = hcol[(4 * j + 1) * N];
            h[j].z = hcol[(4 * j + 2) * N];
            h[j].w = hcol[(4 * j + 3) * N];
        }
    }

    float x_i = 0.f, g_i = 0.f, d_i = 0.f;
    if (half == 0) {
        x_i = x0[p * N + i];
        sm.d[i] = x_i;                 // stage x in d slot
        sm.s[1][i]  = 0.f;             // "prev" buffers for iter 0 (pending=0)
        sm.Hy[1][i] = 0.f;
    }
    __syncthreads();

    // ---- g0 = Q x0 - b ----
    {
        const float4* dv = reinterpret_cast<const float4*>(sm.d + kbase);
        float part = 0.f;
        #pragma unroll 4
        for (int j = 0; j < 16; j++) {
            float4 v = dv[j];
            part += qcol[(4 * j + 0) * N] * v.x;
            part += qcol[(4 * j + 1) * N] * v.y;
            part += qcol[(4 * j + 2) * N] * v.z;
            part += qcol[(4 * j + 3) * N] * v.w;
        }
        sm.qp[t] = part;
    }
    __syncthreads();
    if (half == 0) {
        g_i = sm.qp[i] + sm.qp[128 + i] - bvec[p * N + i];
        sm.g[i] = g_i;
    }
    __syncthreads();

    // ---- d0 = -H g0 ----
    {
        const float4* gv = reinterpret_cast<const float4*>(sm.g + kbase);
        float dp = 0.f;
        #pragma unroll
        for (int k = 0; k < 16; k++) {
            float4 v = gv[k];
            dp += h[k].x * v.x; dp += h[k].y * v.y;
            dp += h[k].z * v.z; dp += h[k].w * v.w;
        }
        sm.qp[t] = dp;
    }
    __syncthreads();
    if (half == 0) {
        d_i = -(sm.qp[i] + sm.qp[128 + i]);
        sm.d[i] = d_i;
    }
    __syncthreads();

    bool  mask = true;                 // block-uniform "updating" flag
    float a_p = 0.f, b_p = 0.f;        // pending lazy H-update row coefficients

    for (int it = 0; it < MAXIT; ++it) {
        const int cur = it & 1, prev = cur ^ 1;

        // ===== Phase A: qd = Q d; reduce g.d, d.Qd; alpha, s, dg =====
        float qdp = 0.f;
        {
            const float4* dv = reinterpret_cast<const float4*>(sm.d + kbase);
            #pragma unroll 4
            for (int j = 0; j < 16; j++) {
                float4 v = dv[j];
                qdp += qcol[(4 * j + 0) * N] * v.x;
                qdp += qcol[(4 * j + 1) * N] * v.y;
                qdp += qcol[(4 * j + 2) * N] * v.z;
                qdp += qcol[(4 * j + 3) * N] * v.w;
            }
        }
        sm.qp[t] = qdp;
        float gdp  = (half == 0) ? g_i * d_i : 0.f;
        float dqdp = sm.d[i] * qdp;            // sum_t = d.Qd
        block_sum2(gdp, dqdp, sm.red, t);      // publishes qp too
        const float gd = gdp, dqd = dqdp;

        const float alpha = -gd / fmaxf(dqd, 1e-12f);
        const float sdg   = alpha * alpha * dqd;       // s.dg exactly

        float s_i = 0.f, gn_i = 0.f;
        if (half == 0) {
            const float qd_i = sm.qp[i] + sm.qp[128 + i];
            const float dg_i = alpha * qd_i;           // dg = a*Qd (quadratic)
            gn_i = g_i + dg_i;
            s_i  = alpha * d_i;
            sm.dg[i]     = dg_i;
            sm.s[cur][i] = s_i;
        }
        __syncthreads();                               // dg, s[cur] visible

        // ===== Phase B: apply pending H-update, fused Hy = H dg =====
        float hp = 0.f;
        {
            const float4* sp = reinterpret_cast<const float4*>(sm.s[prev]  + kbase);
            const float4* yp = reinterpret_cast<const float4*>(sm.Hy[prev] + kbase);
            const float4* yv = reinterpret_cast<const float4*>(sm.dg       + kbase);
            #pragma unroll
            for (int k = 0; k < 16; k++) {
                float4 sv = sp[k], pv = yp[k], v = yv[k];
                h[k].x += a_p * sv.x - b_p * pv.x;  hp += h[k].x * v.x;
                h[k].y += a_p * sv.y - b_p * pv.y;  hp += h[k].y * v.y;
                h[k].z += a_p * sv.z - b_p * pv.z;  hp += h[k].z * v.z;
                h[k].w += a_p * sv.w - b_p * pv.w;  hp += h[k].w * v.w;
            }
        }
        sm.qp[t] = hp;
        float ihp = sm.dg[i] * hp;             // sum_t = dg . Hy
        float e2p = 0.f;
        if (half == 0) {
            const float gc = mask ? gn_i : g_i;        // commit with OLD mask
            const float xc = mask ? x_i + s_i : x_i;
            g_i = gc; x_i = xc;
            e2p = gc * gc;
        }
        block_sum2(ihp, e2p, sm.red, t);       // publishes qp
        const float ihdg = ihp, err2 = e2p;

        // per-row Hy from qp combine (valid for ALL threads)
        const float hy_row = sm.qp[i] + sm.qp[128 + i];
        const float s_row  = sm.s[cur][i];
        if (half == 0) sm.Hy[cur][i] = hy_row;

        // new pending coefficients (sdg==0 -> dH = 0, as reference)
        const bool  nz  = (sdg != 0.0f);
        const float biv = nz ? 1.0f / sdg : 0.0f;
        const float c1  = nz ? (sdg + ihdg) * biv * biv : 0.0f;
        a_p = s_row * c1 - biv * hy_row;       // coeff of s_prev[j]
        b_p = biv * s_row;                     // coeff of Hy_prev[j]

        // ===== Phase C: d_next = -H_new g_new via scalar recurrence =====
        // s.g = alpha*gd ; Hy.g = -alpha*dqd  (both already reduced)
        const float m    = mask ? 1.0f : 0.0f;
        const float sgn  = alpha * gd + m * sdg;           // s . g_committed
        const float hygn = m * ihdg - alpha * dqd;         // Hy . g_committed
        const float cs   = biv * hygn - c1 * sgn;
        const float ch   = biv * sgn - m;
        if (half == 0) {
            d_i = d_i + cs * s_i + ch * hy_row;            // == -H_new g_new
            sm.d[i] = d_i;
        }
        mask = mask && (err2 > 1e-12f);        // err>1e-6 <=> err^2>1e-12
        __syncthreads();                       // d, Hy[cur] visible
    }

    if (half == 0) out[p * N + i] = x_i;
}

extern "C" void kernel_launch(void* const* d_in, const int* in_sizes, int n_in,
                              void* d_out, int out_size)
{
    const float* Hinit = (const float*)d_in[0];
    const float* Q     = (const float*)d_in[1];
    const float* bvec  = (const float*)d_in[2];
    const float* x0    = (const float*)d_in[3];
    float*       out   = (float*)d_out;

    const int nprob = out_size / N;    // B*E = 1024
    bfgs_kernel<<<nprob, 256>>>(Hinit, Q, bvec, x0, out);
}

// round 9
// speedup vs baseline: 1.5708x; 1.0504x over previous
#include <cuda_runtime.h>

constexpr int N     = 128;
constexpr int MAXIT = 8;

struct SM {
    __align__(16) float d  [N];
    __align__(16) float g  [N];          // prologue only
    __align__(16) float dg [N];
    __align__(16) float s  [2][N];       // double-buffered (lazy H update)
    __align__(16) float Hy [2][N];
    __align__(16) float qpA[8 * 128];    // Phase-A partials, scalar view [r][col]
    __align__(16) float qpB[2 * N];      // Phase-B partials (owner mapping)
    __align__(16) float redA[16];
    __align__(16) float redB[16];
};

__device__ __forceinline__ float warp_sum(float v) {
    #pragma unroll
    for (int o = 16; o > 0; o >>= 1) v += __shfl_xor_sync(0xffffffffu, v, o);
    return v;
}

// Q-matvec partial: cols 4c..4c+3, rows [16r,16r+16). 16 LDG.128 total.
__device__ __forceinline__ float4 qmv_part(const float* __restrict__ Q,
                                           const float* dvec, int c, int r) {
    const float4* qr4 = reinterpret_cast<const float4*>(Q + (size_t)(16 * r) * N) + c;
    const float4* dk  = reinterpret_cast<const float4*>(dvec + 16 * r);
    float4 acc = make_float4(0.f, 0.f, 0.f, 0.f);
    #pragma unroll 2
    for (int jj = 0; jj < 4; jj++) {
        float4 dv = dk[jj];
        float4 q0 = qr4[(4 * jj + 0) * 32];
        float4 q1 = qr4[(4 * jj + 1) * 32];
        float4 q2 = qr4[(4 * jj + 2) * 32];
        float4 q3 = qr4[(4 * jj + 3) * 32];
        acc.x += q0.x * dv.x + q1.x * dv.y + q2.x * dv.z + q3.x * dv.w;
        acc.y += q0.y * dv.x + q1.y * dv.y + q2.y * dv.z + q3.y * dv.w;
        acc.z += q0.z * dv.x + q1.z * dv.y + q2.z * dv.z + q3.z * dv.w;
        acc.w += q0.w * dv.x + q1.w * dv.y + q2.w * dv.z + q3.w * dv.w;
    }
    return acc;
}

__device__ __forceinline__ float combine8(const float* qpA, int i) {
    float s = 0.f;
    #pragma unroll
    for (int r = 0; r < 8; r++) s += qpA[r * 128 + i];
    return s;
}

__global__ __launch_bounds__(256, 2)
void bfgs_kernel(const float* __restrict__ Hinit,
                 const float* __restrict__ Q,
                 const float* __restrict__ bvec,
                 const float* __restrict__ x0,
                 float* __restrict__ out)
{
    __shared__ SM sm;

    const int t     = threadIdx.x;
    const int i     = t & 127;         // owner mapping: row/element i
    const int half  = t >> 7;
    const int kbase = half * 64;
    const int c     = t & 31;          // Phase-A mapping: column group
    const int r     = t >> 5;          // Phase-A mapping: k-range (== warp id)
    const int p     = blockIdx.x;

    float4* qpA4 = reinterpret_cast<float4*>(sm.qpA);

    // ---- H chunk -> registers via the coalesced TRANSPOSE (H symmetric) ----
    float4 h[16];
    {
        const float* hcol = Hinit + (size_t)kbase * N + i;
        #pragma unroll 4
        for (int j = 0; j < 16; j++) {
            h[j].x = hcol[(4 * j + 0) * N];
            h[j].y = hcol[(4 * j + 1) * N];
            h[j].z = hcol[(4 * j + 2) * N];
            h[j].w = hcol[(4 * j + 3) * N];
        }
    }

    float x_i = 0.f, g_i = 0.f, d_i = 0.f;
    if (half == 0) {
        x_i = x0[p * N + i];
        sm.d[i] = x_i;
        sm.s[1][i]  = 0.f;             // pending=0 for iter 0 (prev buffer)
        sm.Hy[1][i] = 0.f;
    }
    __syncthreads();

    // ---- g0 = Q x0 - b ----
    qpA4[t] = qmv_part(Q, sm.d, c, r);
    __syncthreads();
    if (half == 0) {
        g_i = combine8(sm.qpA, i) - bvec[p * N + i];
        sm.g[i] = g_i;
    }
    __syncthreads();

    // ---- d0 = -H g0 ----
    {
        const float4* gv = reinterpret_cast<const float4*>(sm.g + kbase);
        float dp = 0.f;
        #pragma unroll
        for (int k = 0; k < 16; k++) {
            float4 v = gv[k];
            dp += h[k].x * v.x; dp += h[k].y * v.y;
            dp += h[k].z * v.z; dp += h[k].w * v.w;
        }
        sm.qpB[t] = dp;
    }
    __syncthreads();
    if (half == 0) {
        d_i = -(sm.qpB[i] + sm.qpB[128 + i]);
        sm.d[i] = d_i;
    }
    __syncthreads();

    bool  mask = true;
    float a_p = 0.f, b_p = 0.f;        // pending lazy H-update coefficients

    for (int it = 0; it < MAXIT; ++it) {
        const int cur = it & 1, prev = cur ^ 1;

        // ===== Phase A: qd = Q d (LDG.128 mapping); gd, dQd; alpha, s, dg =====
        float4 acc = qmv_part(Q, sm.d, c, r);
        qpA4[t] = acc;
        float4 dq4 = reinterpret_cast<const float4*>(sm.d)[c];
        float dqdp = acc.x * dq4.x + acc.y * dq4.y + acc.z * dq4.z + acc.w * dq4.w;
        float gdp  = (half == 0) ? g_i * d_i : 0.f;
        gdp  = warp_sum(gdp);
        dqdp = warp_sum(dqdp);
        if ((t & 31) == 0) { sm.redA[r] = gdp; sm.redA[8 + r] = dqdp; }
        __syncthreads();                                    // S1: qpA + redA
        float gd, dqd;
        {
            const float4* r4 = reinterpret_cast<const float4*>(sm.redA);
            float4 A = r4[0], B = r4[1], C = r4[2], D = r4[3];
            gd  = (A.x + A.y) + (A.z + A.w) + (B.x + B.y) + (B.z + B.w);
            dqd = (C.x + C.y) + (C.z + C.w) + (D.x + D.y) + (D.z + D.w);
        }

        const float alpha = -gd / fmaxf(dqd, 1e-12f);
        const float sdg   = alpha * alpha * dqd;            // s.dg exactly

        float s_i = 0.f, gn_i = 0.f;
        if (half == 0) {
            const float qd_i = combine8(sm.qpA, i);
            const float dg_i = alpha * qd_i;                // dg = a*Qd (quadratic)
            gn_i = g_i + dg_i;
            s_i  = alpha * d_i;
            sm.dg[i]     = dg_i;
            sm.s[cur][i] = s_i;
        }
        __syncthreads();                                    // S2: dg, s[cur]

        // ===== Phase B: apply pending H-update fused with Hy = H dg =====
        float hp = 0.f;
        {
            const float4* sp = reinterpret_cast<const float4*>(sm.s[prev]  + kbase);
            const float4* yp = reinterpret_cast<const float4*>(sm.Hy[prev] + kbase);
            const float4* yv = reinterpret_cast<const float4*>(sm.dg       + kbase);
            #pragma unroll
            for (int k = 0; k < 16; k++) {
                float4 sv = sp[k], pv = yp[k], v = yv[k];
                h[k].x += a_p * sv.x - b_p * pv.x;  hp += h[k].x * v.x;
                h[k].y += a_p * sv.y - b_p * pv.y;  hp += h[k].y * v.y;
                h[k].z += a_p * sv.z - b_p * pv.z;  hp += h[k].z * v.z;
                h[k].w += a_p * sv.w - b_p * pv.w;  hp += h[k].w * v.w;
            }
        }
        sm.qpB[t] = hp;
        float ihp = sm.dg[i] * hp;                          // sum_t = dg.Hy
        float e2p = 0.f;
        if (half == 0) {
            const float gc = mask ? gn_i : g_i;             // commit, OLD mask
            const float xc = mask ? x_i + s_i : x_i;
            g_i = gc; x_i = xc;
            e2p = gc * gc;
        }
        ihp = warp_sum(ihp);
        e2p = warp_sum(e2p);
        if ((t & 31) == 0) { sm.redB[r] = ihp; sm.redB[8 + r] = e2p; }
        __syncthreads();                                    // S3: qpB + redB
        float ihdg, err2;
        {
            const float4* r4 = reinterpret_cast<const float4*>(sm.redB);
            float4 A = r4[0], B = r4[1], C = r4[2], D = r4[3];
            ihdg = (A.x + A.y) + (A.z + A.w) + (B.x + B.y) + (B.z + B.w);
            err2 = (C.x + C.y) + (C.z + C.w) + (D.x + D.y) + (D.z + D.w);
        }

        // per-row Hy / s (valid on ALL threads; both halves of row i need them)
        const float hy_row = sm.qpB[i] + sm.qpB[128 + i];
        const float s_row  = sm.s[cur][i];

        const bool  nz  = (sdg != 0.0f);
        const float biv = nz ? 1.0f / sdg : 0.0f;
        const float c1  = nz ? (sdg + ihdg) * biv * biv : 0.0f;
        a_p = s_row * c1 - biv * hy_row;                    // pending coeffs
        b_p = biv * s_row;

        // ===== Phase C: d_next = -H_new g_new via scalar recurrence =====
        const float m    = mask ? 1.0f : 0.0f;
        const float sgn  = alpha * gd + m * sdg;            // s . g_committed
        const float hygn = m * ihdg - alpha * dqd;          // Hy . g_committed
        const float cs   = biv * hygn - c1 * sgn;
        const float ch   = biv * sgn - m;
        if (half == 0) {
            d_i = d_i + cs * s_i + ch * hy_row;             // == -H_new g_new
            sm.d[i] = d_i;
            sm.Hy[cur][i] = hy_row;
        }
        mask = mask && (err2 > 1e-12f);                     // err>1e-6
        __syncthreads();                                    // S4: d, Hy[cur]
    }

    if (half == 0) out[p * N + i] = x_i;
}

extern "C" void kernel_launch(void* const* d_in, const int* in_sizes, int n_in,
                              void* d_out, int out_size)
{
    const float* Hinit = (const float*)d_in[0];
    const float* Q     = (const float*)d_in[1];
    const float* bvec  = (const float*)d_in[2];
    const float* x0    = (const float*)d_in[3];
    float*       out   = (float*)d_out;

    const int nprob = out_size / N;    // B*E = 1024
    bfgs_kernel<<<nprob, 256>>>(Hinit, Q, bvec, x0, out);
}

// round 11
// speedup vs baseline: 2.4727x; 1.5742x over previous
#include <cuda_runtime.h>

constexpr int N     = 128;
constexpr int MAXIT = 8;

__device__ int g_hid;   // 1 if Hinit == identity

__global__ void check_hinit_kernel(const float* __restrict__ Hinit) {
    int ok = 1;
    for (int idx = threadIdx.x; idx < N * N; idx += blockDim.x) {
        const float e = ((idx / N) == (idx % N)) ? 1.f : 0.f;
        if (Hinit[idx] != e) ok = 0;
    }
    ok = __syncthreads_and(ok);
    if (threadIdx.x == 0) g_hid = ok;
}

struct SM {
    __align__(16) float d  [N];
    __align__(16) float dg [N];
    __align__(16) float sH [MAXIT][N];   // step history
    __align__(16) float yH [MAXIT][N];   // Hy history
    __align__(16) float qpA[8 * 128];    // matvec partials [r][col]
    __align__(16) float sig[8];          // s_j . dg
    __align__(16) float eta[8];          // Hy_j . dg
    __align__(16) float c1a[8];          // stored c1_j
    __align__(16) float bva[8];          // stored biv_j
    __align__(16) float redA[16];
    __align__(16) float redB[16];
};

__device__ __forceinline__ float warp_sum(float v) {
    #pragma unroll
    for (int o = 16; o > 0; o >>= 1) v += __shfl_xor_sync(0xffffffffu, v, o);
    return v;
}

// Q-matvec partial: cols 4c..4c+3, rows [16r,16r+16). 16 LDG.128 total.
__device__ __forceinline__ float4 qmv_part(const float* __restrict__ Q,
                                           const float* dvec, int c, int r) {
    const float4* qr4 = reinterpret_cast<const float4*>(Q + (size_t)(16 * r) * N) + c;
    const float4* dk  = reinterpret_cast<const float4*>(dvec + 16 * r);
    float4 acc = make_float4(0.f, 0.f, 0.f, 0.f);
    #pragma unroll 2
    for (int jj = 0; jj < 4; jj++) {
        float4 dv = dk[jj];
        float4 q0 = qr4[(4 * jj + 0) * 32];
        float4 q1 = qr4[(4 * jj + 1) * 32];
        float4 q2 = qr4[(4 * jj + 2) * 32];
        float4 q3 = qr4[(4 * jj + 3) * 32];
        acc.x += q0.x * dv.x + q1.x * dv.y + q2.x * dv.z + q3.x * dv.w;
        acc.y += q0.y * dv.x + q1.y * dv.y + q2.y * dv.z + q3.y * dv.w;
        acc.z += q0.z * dv.x + q1.z * dv.y + q2.z * dv.z + q3.z * dv.w;
        acc.w += q0.w * dv.x + q1.w * dv.y + q2.w * dv.z + q3.w * dv.w;
    }
    return acc;
}

__device__ __forceinline__ float combine8(const float* qpA, int i) {
    float s = 0.f;
    #pragma unroll
    for (int r = 0; r < 8; r++) s += qpA[r * 128 + i];
    return s;
}

// general-path row dot: (Hinit v)_i, v in smem
__device__ __forceinline__ float rowdot(const float* __restrict__ Hrow,
                                        const float* v) {
    const float4* h4 = reinterpret_cast<const float4*>(Hrow);
    const float4* v4 = reinterpret_cast<const float4*>(v);
    float acc = 0.f;
    #pragma unroll 8
    for (int k = 0; k < 32; k++) {
        float4 hh = h4[k], vv = v4[k];
        acc += hh.x * vv.x + hh.y * vv.y + hh.z * vv.z + hh.w * vv.w;
    }
    return acc;
}

__global__ __launch_bounds__(256, 4)
void bfgs_kernel(const float* __restrict__ Hinit,
                 const float* __restrict__ Q,
                 const float* __restrict__ bvec,
                 const float* __restrict__ x0,
                 float* __restrict__ out)
{
    __shared__ SM sm;

    const int t    = threadIdx.x;
    const int i    = t & 127;          // owner mapping (half==0 owns element i)
    const int half = t >> 7;
    const int c    = t & 31;           // lane: column group (4c..4c+3)
    const int r    = t >> 5;           // warp id: k-range / history slot
    const int p    = blockIdx.x;

    const int identity = g_hid;        // block-uniform branch
    float4* qpA4 = reinterpret_cast<float4*>(sm.qpA);

    float x_i = 0.f, g_i = 0.f, d_i = 0.f;
    if (half == 0) {
        x_i = x0[p * N + i];
        sm.d[i] = x_i;                 // stage x in d slot
    }
    __syncthreads();

    // ---- g0 = Q x0 - b ----
    qpA4[t] = qmv_part(Q, sm.d, c, r);
    __syncthreads();
    if (half == 0) g_i = combine8(sm.qpA, i) - bvec[p * N + i];

    // ---- d0 = -H0 g0 ----
    if (identity) {
        if (half == 0) { d_i = -g_i; sm.d[i] = d_i; }
        __syncthreads();
    } else {
        if (half == 0) sm.dg[i] = g_i;          // stage g
        __syncthreads();
        if (half == 0) {
            d_i = -rowdot(Hinit + (size_t)i * N, sm.dg);
            sm.d[i] = d_i;
        }
        __syncthreads();
    }

    bool mask = true;   // block-uniform "updating" flag

    for (int it = 0; it < MAXIT; ++it) {
        // ===== Phase A: qd = Q d; gd, dQd; alpha, s, dg =====
        float4 acc = qmv_part(Q, sm.d, c, r);
        qpA4[t] = acc;
        float4 dq4 = reinterpret_cast<const float4*>(sm.d)[c];
        float dqdp = acc.x * dq4.x + acc.y * dq4.y + acc.z * dq4.z + acc.w * dq4.w;
        float gdp  = (half == 0) ? g_i * d_i : 0.f;
        gdp  = warp_sum(gdp);
        dqdp = warp_sum(dqdp);
        if (c == 0) { sm.redA[r] = gdp; sm.redA[8 + r] = dqdp; }
        __syncthreads();                                  // S1
        float gd, dqd;
        {
            const float4* r4 = reinterpret_cast<const float4*>(sm.redA);
            float4 A = r4[0], B = r4[1], C = r4[2], D = r4[3];
            gd  = (A.x + A.y) + (A.z + A.w) + (B.x + B.y) + (B.z + B.w);
            dqd = (C.x + C.y) + (C.z + C.w) + (D.x + D.y) + (D.z + D.w);
        }
        const float alpha = -gd / fmaxf(dqd, 1e-12f);
        const float sdg   = alpha * alpha * dqd;          // s.dg exactly

        float s_i = 0.f, gn_i = 0.f, dg_i = 0.f;
        if (half == 0) {
            const float qd_i = combine8(sm.qpA, i);
            dg_i = alpha * qd_i;                          // dg = a*Qd (quadratic)
            gn_i = g_i + dg_i;
            s_i  = alpha * d_i;
            sm.dg[i]      = dg_i;
            sm.sH[it][i]  = s_i;
        }
        __syncthreads();                                  // S2

        // ===== dots vs history: warp r handles slot j = r (j < it) =====
        float sp = 0.f, ep = 0.f;
        if (r < it) {
            const float4* s4 = reinterpret_cast<const float4*>(sm.sH[r]);
            const float4* y4 = reinterpret_cast<const float4*>(sm.yH[r]);
            float4 dv = reinterpret_cast<const float4*>(sm.dg)[c];
            float4 sv = s4[c], yv = y4[c];
            sp = sv.x * dv.x + sv.y * dv.y + sv.z * dv.z + sv.w * dv.w;
            ep = yv.x * dv.x + yv.y * dv.y + yv.z * dv.z + yv.w * dv.w;
        }
        sp = warp_sum(sp); ep = warp_sum(ep);
        if (c == 0) { sm.sig[r] = sp; sm.eta[r] = ep; }

        // general-path base u = Hinit*dg (never taken when Hinit == I)
        float u_i = dg_i;
        if (!identity && half == 0)
            u_i = rowdot(Hinit + (size_t)i * N, sm.dg);
        __syncthreads();                                  // S3

        // ===== Hy = H dg via low-rank combination (owners) =====
        float hy = 0.f, ihp = 0.f, e2p = 0.f;
        if (half == 0) {
            hy = u_i;
            #pragma unroll
            for (int j = 0; j < MAXIT; ++j) {
                if (j < it) {
                    const float c1j = sm.c1a[j], bj = sm.bva[j];
                    const float sgj = sm.sig[j], etj = sm.eta[j];
                    const float wj = c1j * sgj - bj * etj;
                    const float vj = -bj * sgj;
                    hy += wj * sm.sH[j][i] + vj * sm.yH[j][i];
                }
            }
            ihp = dg_i * hy;                              // -> ihdg
            const float gc = mask ? gn_i : g_i;           // commit, OLD mask
            const float xc = mask ? x_i + s_i : x_i;
            g_i = gc; x_i = xc;
            e2p = gc * gc;                                // -> ||g||^2
        }
        ihp = warp_sum(ihp); e2p = warp_sum(e2p);
        if (c == 0) { sm.redB[r] = ihp; sm.redB[8 + r] = e2p; }
        __syncthreads();                                  // S4
        float ihdg, err2;
        {
            const float4* r4 = reinterpret_cast<const float4*>(sm.redB);
            float4 A = r4[0], B = r4[1], C = r4[2], D = r4[3];
            ihdg = (A.x + A.y) + (A.z + A.w) + (B.x + B.y) + (B.z + B.w);
            err2 = (C.x + C.y) + (C.z + C.w) + (D.x + D.y) + (D.z + D.w);
        }

        // coefficients (sdg == 0 -> dH = 0, as reference)
        const bool  nz  = (sdg != 0.0f);
        const float biv = nz ? 1.0f / sdg : 0.0f;
        const float c1  = nz ? (sdg + ihdg) * biv * biv : 0.0f;

        // ===== d_next = -H_new g_new via scalar recurrence =====
        const float m    = mask ? 1.0f : 0.0f;
        const float sgn  = alpha * gd + m * sdg;          // s . g_committed
        const float hygn = m * ihdg - alpha * dqd;        // Hy . g_committed
        const float cs   = biv * hygn - c1 * sgn;
        const float ch   = biv * sgn - m;
        if (half == 0) {
            d_i = d_i + cs * s_i + ch * hy;               // hy still in register
            sm.d[i]      = d_i;
            sm.yH[it][i] = hy;
        }
        if (t == 0) { sm.c1a[it] = c1; sm.bva[it] = biv; }
        mask = mask && (err2 > 1e-12f);                   // err>1e-6
        __syncthreads();                                  // S5
    }

    if (half == 0) out[p * N + i] = x_i;
}

extern "C" void kernel_launch(void* const* d_in, const int* in_sizes, int n_in,
                              void* d_out, int out_size)
{
    const float* Hinit = (const float*)d_in[0];
    const float* Q     = (const float*)d_in[1];
    const float* bvec  = (const float*)d_in[2];
    const float* x0    = (const float*)d_in[3];
    float*       out   = (float*)d_out;

    const int nprob = out_size / N;    // B*E = 1024
    check_hinit_kernel<<<1, 256>>>(Hinit);
    bfgs_kernel<<<nprob, 256>>>(Hinit, Q, bvec, x0, out);
}

// round 12
// speedup vs baseline: 2.7912x; 1.1288x over previous
#include <cuda_runtime.h>

constexpr int N     = 128;
constexpr int MAXIT = 8;

__device__ int g_hid;   // 1 if Hinit == identity

__global__ void check_hinit_kernel(const float* __restrict__ Hinit) {
    int ok = 1;
    for (int idx = threadIdx.x; idx < N * N; idx += blockDim.x) {
        const float e = ((idx / N) == (idx % N)) ? 1.f : 0.f;
        if (Hinit[idx] != e) ok = 0;
    }
    ok = __syncthreads_and(ok);
    if (threadIdx.x == 0) g_hid = ok;
}

// Two problems per CTA. Owner mapping: thread t -> (prob = t>>7, elem = t&127).
struct SM {
    __align__(16) float d  [2][N];
    __align__(16) float dg [2][N];
    __align__(16) float sH [2][MAXIT][N];
    __align__(16) float yH [2][MAXIT][N];
    __align__(16) float qpA[2][8 * 128];   // matvec partials [prob][r][col]
    __align__(16) float sig[2][8];
    __align__(16) float eta[2][8];
    __align__(16) float c1a[2][8];
    __align__(16) float bva[2][8];
    __align__(16) float redA[32];          // gd0,gd1,dqd0,dqd1 x 8 warps
    __align__(16) float redB[32];          // ih0,ih1,e20,e21  x 8 warps
};

__device__ __forceinline__ float warp_sum(float v) {
    #pragma unroll
    for (int o = 16; o > 0; o >>= 1) v += __shfl_xor_sync(0xffffffffu, v, o);
    return v;
}

// Q-matvec partials for BOTH problems sharing each Q load.
// Thread (c, r): cols 4c..4c+3, rows [16r, 16r+16). 16 LDG.128 total.
__device__ __forceinline__ void qmv_part2(const float* __restrict__ Q,
                                          const float* d0, const float* d1,
                                          int c, int r, float4& A0, float4& A1) {
    const float4* qr4 = reinterpret_cast<const float4*>(Q + (size_t)(16 * r) * N) + c;
    const float4* k0  = reinterpret_cast<const float4*>(d0 + 16 * r);
    const float4* k1  = reinterpret_cast<const float4*>(d1 + 16 * r);
    A0 = make_float4(0.f, 0.f, 0.f, 0.f);
    A1 = A0;
    #pragma unroll 2
    for (int jj = 0; jj < 4; jj++) {
        float4 u = k0[jj], v = k1[jj];
        float4 q0 = qr4[(4 * jj + 0) * 32];
        float4 q1 = qr4[(4 * jj + 1) * 32];
        float4 q2 = qr4[(4 * jj + 2) * 32];
        float4 q3 = qr4[(4 * jj + 3) * 32];
        A0.x += q0.x * u.x + q1.x * u.y + q2.x * u.z + q3.x * u.w;
        A0.y += q0.y * u.x + q1.y * u.y + q2.y * u.z + q3.y * u.w;
        A0.z += q0.z * u.x + q1.z * u.y + q2.z * u.z + q3.z * u.w;
        A0.w += q0.w * u.x + q1.w * u.y + q2.w * u.z + q3.w * u.w;
        A1.x += q0.x * v.x + q1.x * v.y + q2.x * v.z + q3.x * v.w;
        A1.y += q0.y * v.x + q1.y * v.y + q2.y * v.z + q3.y * v.w;
        A1.z += q0.z * v.x + q1.z * v.y + q2.z * v.z + q3.z * v.w;
        A1.w += q0.w * v.x + q1.w * v.y + q2.w * v.z + q3.w * v.w;
    }
}

__device__ __forceinline__ float combine8(const float* qpA, int i) {
    float s = 0.f;
    #pragma unroll
    for (int r = 0; r < 8; r++) s += qpA[r * 128 + i];
    return s;
}

// general-path row dot for arbitrary Hinit
__device__ __forceinline__ float rowdot(const float* __restrict__ Hrow,
                                        const float* v) {
    const float4* h4 = reinterpret_cast<const float4*>(Hrow);
    const float4* v4 = reinterpret_cast<const float4*>(v);
    float acc = 0.f;
    #pragma unroll 8
    for (int k = 0; k < 32; k++) {
        float4 hh = h4[k], vv = v4[k];
        acc += hh.x * vv.x + hh.y * vv.y + hh.z * vv.z + hh.w * vv.w;
    }
    return acc;
}

__global__ __launch_bounds__(256, 3)
void bfgs_kernel(const float* __restrict__ Hinit,
                 const float* __restrict__ Q,
                 const float* __restrict__ bvec,
                 const float* __restrict__ x0,
                 float* __restrict__ out)
{
    __shared__ SM sm;

    const int t    = threadIdx.x;
    const int i    = t & 127;          // owned element
    const int half = t >> 7;           // owned problem (0/1) within pair
    const int c    = t & 31;           // matvec: column group (4c..4c+3)
    const int r    = t >> 5;           // matvec: k-range / history slot (warp id)
    const int p    = 2 * blockIdx.x + half;   // global problem of this owner

    const int identity = g_hid;
    float4* qp0 = reinterpret_cast<float4*>(sm.qpA[0]);
    float4* qp1 = reinterpret_cast<float4*>(sm.qpA[1]);

    // ---- stage x0 for both problems (owner write) ----
    float x_i = x0[p * N + i];
    sm.d[half][i] = x_i;
    __syncthreads();

    // ---- g0 = Q x0 - b (shared Q loads) ----
    {
        float4 A0, A1;
        qmv_part2(Q, sm.d[0], sm.d[1], c, r, A0, A1);
        qp0[t] = A0; qp1[t] = A1;
    }
    __syncthreads();
    float g_i = combine8(sm.qpA[half], i) - bvec[p * N + i];

    // ---- d0 = -H0 g0 ----
    float d_i;
    if (identity) {
        d_i = -g_i;
        sm.d[half][i] = d_i;
        __syncthreads();
    } else {
        sm.dg[half][i] = g_i;
        __syncthreads();
        d_i = -rowdot(Hinit + (size_t)i * N, sm.dg[half]);
        sm.d[half][i] = d_i;
        __syncthreads();
    }

    bool mask = true;   // own problem's "updating" flag (uniform within half)

    for (int it = 0; it < MAXIT; ++it) {
        // ===== Phase A: qd = Q d both problems; gd, dQd; alpha, s, dg =====
        float4 A0, A1;
        qmv_part2(Q, sm.d[0], sm.d[1], c, r, A0, A1);
        qp0[t] = A0; qp1[t] = A1;
        float4 u4 = reinterpret_cast<const float4*>(sm.d[0])[c];
        float4 v4 = reinterpret_cast<const float4*>(sm.d[1])[c];
        float dq0 = A0.x * u4.x + A0.y * u4.y + A0.z * u4.z + A0.w * u4.w;
        float dq1 = A1.x * v4.x + A1.y * v4.y + A1.z * v4.z + A1.w * v4.w;
        float gd0 = (half == 0) ? g_i * d_i : 0.f;
        float gd1 = (half == 1) ? g_i * d_i : 0.f;
        gd0 = warp_sum(gd0); gd1 = warp_sum(gd1);
        dq0 = warp_sum(dq0); dq1 = warp_sum(dq1);
        if (c == 0) {
            sm.redA[r] = gd0; sm.redA[8 + r]  = gd1;
            sm.redA[16 + r] = dq0; sm.redA[24 + r] = dq1;
        }
        __syncthreads();                                   // S1
        float gd, dqd;
        {
            const float4* r4 = reinterpret_cast<const float4*>(sm.redA);
            float4 a = r4[0], b = r4[1], cc = r4[2], dd = r4[3];
            float4 e = r4[4], f = r4[5], gg = r4[6], hh = r4[7];
            const float GD0 = (a.x + a.y) + (a.z + a.w) + (b.x + b.y) + (b.z + b.w);
            const float GD1 = (cc.x + cc.y) + (cc.z + cc.w) + (dd.x + dd.y) + (dd.z + dd.w);
            const float DQ0 = (e.x + e.y) + (e.z + e.w) + (f.x + f.y) + (f.z + f.w);
            const float DQ1 = (gg.x + gg.y) + (gg.z + gg.w) + (hh.x + hh.y) + (hh.z + hh.w);
            gd  = half ? GD1 : GD0;
            dqd = half ? DQ1 : DQ0;
        }
        const float alpha = -gd / fmaxf(dqd, 1e-12f);
        const float sdg   = alpha * alpha * dqd;           // s.dg exactly

        const float qd_i = combine8(sm.qpA[half], i);
        const float dg_i = alpha * qd_i;                   // dg = a*Qd (quadratic)
        const float gn_i = g_i + dg_i;
        const float s_i  = alpha * d_i;
        sm.dg[half][i]     = dg_i;
        sm.sH[half][it][i] = s_i;
        __syncthreads();                                   // S2

        // ===== history dots: warp r handles slot j=r for BOTH problems =====
        if (r < it) {
            float4 dv0 = reinterpret_cast<const float4*>(sm.dg[0])[c];
            float4 dv1 = reinterpret_cast<const float4*>(sm.dg[1])[c];
            float4 s0 = reinterpret_cast<const float4*>(sm.sH[0][r])[c];
            float4 y0 = reinterpret_cast<const float4*>(sm.yH[0][r])[c];
            float4 s1 = reinterpret_cast<const float4*>(sm.sH[1][r])[c];
            float4 y1 = reinterpret_cast<const float4*>(sm.yH[1][r])[c];
            float sp0 = s0.x * dv0.x + s0.y * dv0.y + s0.z * dv0.z + s0.w * dv0.w;
            float ep0 = y0.x * dv0.x + y0.y * dv0.y + y0.z * dv0.z + y0.w * dv0.w;
            float sp1 = s1.x * dv1.x + s1.y * dv1.y + s1.z * dv1.z + s1.w * dv1.w;
            float ep1 = y1.x * dv1.x + y1.y * dv1.y + y1.z * dv1.z + y1.w * dv1.w;
            sp0 = warp_sum(sp0); ep0 = warp_sum(ep0);
            sp1 = warp_sum(sp1); ep1 = warp_sum(ep1);
            if (c == 0) {
                sm.sig[0][r] = sp0; sm.eta[0][r] = ep0;
                sm.sig[1][r] = sp1; sm.eta[1][r] = ep1;
            }
        }
        // general-path base u = Hinit*dg (not taken when Hinit == I)
        float u_i = dg_i;
        if (!identity) u_i = rowdot(Hinit + (size_t)i * N, sm.dg[half]);
        __syncthreads();                                   // S3

        // ===== Hy = H dg via low-rank combination (all owners) =====
        float hy = u_i;
        #pragma unroll
        for (int j = 0; j < MAXIT; ++j) {
            if (j < it) {
                const float c1j = sm.c1a[half][j], bj = sm.bva[half][j];
                const float sgj = sm.sig[half][j], etj = sm.eta[half][j];
                hy += (c1j * sgj - bj * etj) * sm.sH[half][j][i]
                    - (bj * sgj)             * sm.yH[half][j][i];
            }
        }
        // commit x,g with OLD mask; reduce ihdg + ||g||^2 per problem
        const float gc = mask ? gn_i : g_i;
        const float xc = mask ? x_i + s_i : x_i;
        g_i = gc; x_i = xc;
        float ih0 = (half == 0) ? dg_i * hy : 0.f;
        float ih1 = (half == 1) ? dg_i * hy : 0.f;
        float e20 = (half == 0) ? gc * gc : 0.f;
        float e21 = (half == 1) ? gc * gc : 0.f;
        ih0 = warp_sum(ih0); ih1 = warp_sum(ih1);
        e20 = warp_sum(e20); e21 = warp_sum(e21);
        if (c == 0) {
            sm.redB[r] = ih0; sm.redB[8 + r]  = ih1;
            sm.redB[16 + r] = e20; sm.redB[24 + r] = e21;
        }
        __syncthreads();                                   // S4
        float ihdg, err2;
        {
            const float4* r4 = reinterpret_cast<const float4*>(sm.redB);
            float4 a = r4[0], b = r4[1], cc = r4[2], dd = r4[3];
            float4 e = r4[4], f = r4[5], gg = r4[6], hh = r4[7];
            const float IH0 = (a.x + a.y) + (a.z + a.w) + (b.x + b.y) + (b.z + b.w);
            const float IH1 = (cc.x + cc.y) + (cc.z + cc.w) + (dd.x + dd.y) + (dd.z + dd.w);
            const float E20 = (e.x + e.y) + (e.z + e.w) + (f.x + f.y) + (f.z + f.w);
            const float E21 = (gg.x + gg.y) + (gg.z + gg.w) + (hh.x + hh.y) + (hh.z + hh.w);
            ihdg = half ? IH1 : IH0;
            err2 = half ? E21 : E20;
        }

        // coefficients (sdg == 0 -> dH = 0, as reference)
        const bool  nz  = (sdg != 0.0f);
        const float biv = nz ? 1.0f / sdg : 0.0f;
        const float c1  = nz ? (sdg + ihdg) * biv * biv : 0.0f;

        // ===== d_next = -H_new g_new via scalar recurrence =====
        const float m    = mask ? 1.0f : 0.0f;
        const float sgn  = alpha * gd + m * sdg;           // s . g_committed
        const float hygn = m * ihdg - alpha * dqd;         // Hy . g_committed
        const float cs   = biv * hygn - c1 * sgn;
        const float ch   = biv * sgn - m;
        d_i = d_i + cs * s_i + ch * hy;                    // == -H_new g_new
        sm.d[half][i]      = d_i;
        sm.yH[half][it][i] = hy;
        if (i == 0) { sm.c1a[half][it] = c1; sm.bva[half][it] = biv; }
        mask = mask && (err2 > 1e-12f);                    // err>1e-6
        __syncthreads();                                   // S5
    }

    out[p * N + i] = x_i;
}

extern "C" void kernel_launch(void* const* d_in, const int* in_sizes, int n_in,
                              void* d_out, int out_size)
{
    const float* Hinit = (const float*)d_in[0];
    const float* Q     = (const float*)d_in[1];
    const float* bvec  = (const float*)d_in[2];
    const float* x0    = (const float*)d_in[3];
    float*       out   = (float*)d_out;

    const int nprob = out_size / N;    // B*E = 1024 (even)
    check_hinit_kernel<<<1, 256>>>(Hinit);
    bfgs_kernel<<<nprob / 2, 256>>>(Hinit, Q, bvec, x0, out);
}

// round 13
// speedup vs baseline: 3.2989x; 1.1819x over previous
#include <cuda_runtime.h>

constexpr int N     = 128;
constexpr int MAXIT = 8;
constexpr int P     = 4;      // problems per CTA

__device__ int g_hid;         // 1 if Hinit == identity

__global__ void check_hinit_kernel(const float4* __restrict__ H4) {
    int ok = 1;
    // N*N/4 = 4096 float4
    for (int idx = threadIdx.x; idx < 4096; idx += blockDim.x) {
        const int base = idx * 4;
        const int row  = base >> 7;
        const int col  = base & 127;
        float4 v = H4[idx];
        float4 e = make_float4(row == col ? 1.f : 0.f, row == col + 1 ? 0.f : (row == col + 1 ? 1.f : 0.f), 0.f, 0.f);
        // expected: 1 where row == col+k (k = 0..3)
        e.x = (row == col + 0) ? 1.f : 0.f;
        e.y = (row == col + 1) ? 1.f : 0.f;
        e.z = (row == col + 2) ? 1.f : 0.f;
        e.w = (row == col + 3) ? 1.f : 0.f;
        if (v.x != e.x || v.y != e.y || v.z != e.z || v.w != e.w) ok = 0;
    }
    ok = __syncthreads_and(ok);
    if (threadIdx.x == 0) g_hid = ok;
}

// Dynamic-smem layout (P=4 problems per CTA)
struct SM {
    __align__(16) float d  [P][N];
    __align__(16) float dg [P][N];
    __align__(16) float sH [P][MAXIT][N];
    __align__(16) float yH [P][MAXIT][N];
    __align__(16) float qpA[P][8 * 128];     // matvec partials [prob][r][col]
    __align__(16) float sig[P][8];
    __align__(16) float eta[P][8];
    __align__(16) float c1a[P][8];
    __align__(16) float bva[P][8];
    __align__(16) float redA[8 * 8];         // gd[p] (p=0..3), dqd[p] : x 8 warps
    __align__(16) float redB[8 * 8];         // ih[p], e2[p] : x 8 warps
};

__device__ __forceinline__ float warp_sum(float v) {
    #pragma unroll
    for (int o = 16; o > 0; o >>= 1) v += __shfl_xor_sync(0xffffffffu, v, o);
    return v;
}

__device__ __forceinline__ float combine8(const float* qpA, int i) {
    float s = 0.f;
    #pragma unroll
    for (int r = 0; r < 8; r++) s += qpA[r * 128 + i];
    return s;
}

// final from red[g*8 .. g*8+8)
__device__ __forceinline__ float red_final(const float* red, int g) {
    const float4* r4 = reinterpret_cast<const float4*>(red + g * 8);
    float4 a = r4[0], b = r4[1];
    return (a.x + a.y) + (a.z + a.w) + (b.x + b.y) + (b.z + b.w);
}

// general-path row dot for arbitrary Hinit
__device__ __forceinline__ float rowdot(const float* __restrict__ Hrow,
                                        const float* v) {
    const float4* h4 = reinterpret_cast<const float4*>(Hrow);
    const float4* v4 = reinterpret_cast<const float4*>(v);
    float acc = 0.f;
    #pragma unroll 8
    for (int k = 0; k < 32; k++) {
        float4 hh = h4[k], vv = v4[k];
        acc += hh.x * vv.x + hh.y * vv.y + hh.z * vv.z + hh.w * vv.w;
    }
    return acc;
}

__global__ __launch_bounds__(256, 3)
void bfgs_kernel(const float* __restrict__ Hinit,
                 const float* __restrict__ Q,
                 const float* __restrict__ bvec,
                 const float* __restrict__ x0,
                 float* __restrict__ out)
{
    extern __shared__ char smraw[];
    SM& sm = *reinterpret_cast<SM*>(smraw);

    const int t    = threadIdx.x;
    const int i    = t & 127;          // owned element
    const int half = t >> 7;           // owner probs: half and half+2
    const int c    = t & 31;           // matvec: column group (4c..4c+3)
    const int r    = t >> 5;           // matvec: k-range / history slot (warp id)
    const int pa   = half;             // local prob a
    const int pb   = half + 2;         // local prob b
    const int gpa  = P * blockIdx.x + pa;
    const int gpb  = P * blockIdx.x + pb;

    const int identity = g_hid;

    // ---- stage x0 for all 4 problems (each thread: 2 owners) ----
    float xa = x0[gpa * N + i], xb = x0[gpb * N + i];
    sm.d[pa][i] = xa;  sm.d[pb][i] = xb;
    __syncthreads();

    // ---- matvec helper inlined: partials for all 4 problems ----
    auto qmv4 = [&](float4& A0, float4& A1, float4& A2, float4& A3) {
        const float4* qr4 = reinterpret_cast<const float4*>(Q + (size_t)(16 * r) * N) + c;
        const float4* k0 = reinterpret_cast<const float4*>(sm.d[0] + 16 * r);
        const float4* k1 = reinterpret_cast<const float4*>(sm.d[1] + 16 * r);
        const float4* k2 = reinterpret_cast<const float4*>(sm.d[2] + 16 * r);
        const float4* k3 = reinterpret_cast<const float4*>(sm.d[3] + 16 * r);
        A0 = make_float4(0.f, 0.f, 0.f, 0.f); A1 = A0; A2 = A0; A3 = A0;
        #pragma unroll 1
        for (int jj = 0; jj < 4; jj++) {
            float4 q0 = qr4[(4 * jj + 0) * 32];
            float4 q1 = qr4[(4 * jj + 1) * 32];
            float4 q2 = qr4[(4 * jj + 2) * 32];
            float4 q3 = qr4[(4 * jj + 3) * 32];
            float4 u;
            u = k0[jj];
            A0.x += q0.x*u.x + q1.x*u.y + q2.x*u.z + q3.x*u.w;
            A0.y += q0.y*u.x + q1.y*u.y + q2.y*u.z + q3.y*u.w;
            A0.z += q0.z*u.x + q1.z*u.y + q2.z*u.z + q3.z*u.w;
            A0.w += q0.w*u.x + q1.w*u.y + q2.w*u.z + q3.w*u.w;
            u = k1[jj];
            A1.x += q0.x*u.x + q1.x*u.y + q2.x*u.z + q3.x*u.w;
            A1.y += q0.y*u.x + q1.y*u.y + q2.y*u.z + q3.y*u.w;
            A1.z += q0.z*u.x + q1.z*u.y + q2.z*u.z + q3.z*u.w;
            A1.w += q0.w*u.x + q1.w*u.y + q2.w*u.z + q3.w*u.w;
            u = k2[jj];
            A2.x += q0.x*u.x + q1.x*u.y + q2.x*u.z + q3.x*u.w;
            A2.y += q0.y*u.x + q1.y*u.y + q2.y*u.z + q3.y*u.w;
            A2.z += q0.z*u.x + q1.z*u.y + q2.z*u.z + q3.z*u.w;
            A2.w += q0.w*u.x + q1.w*u.y + q2.w*u.z + q3.w*u.w;
            u = k3[jj];
            A3.x += q0.x*u.x + q1.x*u.y + q2.x*u.z + q3.x*u.w;
            A3.y += q0.y*u.x + q1.y*u.y + q2.y*u.z + q3.y*u.w;
            A3.z += q0.z*u.x + q1.z*u.y + q2.z*u.z + q3.z*u.w;
            A3.w += q0.w*u.x + q1.w*u.y + q2.w*u.z + q3.w*u.w;
        }
    };

    // ---- g0 = Q x0 - b ----
    {
        float4 A0, A1, A2, A3;
        qmv4(A0, A1, A2, A3);
        reinterpret_cast<float4*>(sm.qpA[0])[t] = A0;
        reinterpret_cast<float4*>(sm.qpA[1])[t] = A1;
        reinterpret_cast<float4*>(sm.qpA[2])[t] = A2;
        reinterpret_cast<float4*>(sm.qpA[3])[t] = A3;
    }
    __syncthreads();
    float ga = combine8(sm.qpA[pa], i) - bvec[gpa * N + i];
    float gb = combine8(sm.qpA[pb], i) - bvec[gpb * N + i];

    // ---- d0 = -H0 g0 ----
    float da, db;
    if (identity) {
        da = -ga; db = -gb;
        sm.d[pa][i] = da; sm.d[pb][i] = db;
        __syncthreads();
    } else {
        sm.dg[pa][i] = ga; sm.dg[pb][i] = gb;
        __syncthreads();
        da = -rowdot(Hinit + (size_t)i * N, sm.dg[pa]);
        db = -rowdot(Hinit + (size_t)i * N, sm.dg[pb]);
        sm.d[pa][i] = da; sm.d[pb][i] = db;
        __syncthreads();
    }

    bool ma = true, mb = true;    // per-owner-problem updating flags

    #pragma unroll 1
    for (int it = 0; it < MAXIT; ++it) {
        // ===== Phase A: qd = Q d (4 problems); gd, dQd; alpha, s, dg =====
        float4 A0, A1, A2, A3;
        qmv4(A0, A1, A2, A3);
        reinterpret_cast<float4*>(sm.qpA[0])[t] = A0;
        reinterpret_cast<float4*>(sm.qpA[1])[t] = A1;
        reinterpret_cast<float4*>(sm.qpA[2])[t] = A2;
        reinterpret_cast<float4*>(sm.qpA[3])[t] = A3;
        {
            float4 u0 = reinterpret_cast<const float4*>(sm.d[0])[c];
            float4 u1 = reinterpret_cast<const float4*>(sm.d[1])[c];
            float4 u2 = reinterpret_cast<const float4*>(sm.d[2])[c];
            float4 u3 = reinterpret_cast<const float4*>(sm.d[3])[c];
            float dq0 = A0.x*u0.x + A0.y*u0.y + A0.z*u0.z + A0.w*u0.w;
            float dq1 = A1.x*u1.x + A1.y*u1.y + A1.z*u1.z + A1.w*u1.w;
            float dq2 = A2.x*u2.x + A2.y*u2.y + A2.z*u2.z + A2.w*u2.w;
            float dq3 = A3.x*u3.x + A3.y*u3.y + A3.z*u3.z + A3.w*u3.w;
            // gd contributions: owner (half) supplies probs half and half+2
            float gdA = ga * da, gdB = gb * db;
            float g0 = (half == 0) ? gdA : 0.f;
            float g1 = (half == 1) ? gdA : 0.f;
            float g2 = (half == 0) ? gdB : 0.f;
            float g3 = (half == 1) ? gdB : 0.f;
            g0 = warp_sum(g0); g1 = warp_sum(g1); g2 = warp_sum(g2); g3 = warp_sum(g3);
            dq0 = warp_sum(dq0); dq1 = warp_sum(dq1); dq2 = warp_sum(dq2); dq3 = warp_sum(dq3);
            if (c == 0) {
                sm.redA[0 * 8 + r] = g0;  sm.redA[1 * 8 + r] = g1;
                sm.redA[2 * 8 + r] = g2;  sm.redA[3 * 8 + r] = g3;
                sm.redA[4 * 8 + r] = dq0; sm.redA[5 * 8 + r] = dq1;
                sm.redA[6 * 8 + r] = dq2; sm.redA[7 * 8 + r] = dq3;
            }
        }
        __syncthreads();                                   // S1
        const float gd_a  = red_final(sm.redA, pa);
        const float gd_b  = red_final(sm.redA, pb);
        const float dqd_a = red_final(sm.redA, 4 + pa);
        const float dqd_b = red_final(sm.redA, 4 + pb);

        const float al_a = -gd_a / fmaxf(dqd_a, 1e-12f);
        const float al_b = -gd_b / fmaxf(dqd_b, 1e-12f);
        const float sdg_a = al_a * al_a * dqd_a;
        const float sdg_b = al_b * al_b * dqd_b;

        const float dg_a = al_a * combine8(sm.qpA[pa], i);
        const float dg_b = al_b * combine8(sm.qpA[pb], i);
        const float gn_a = ga + dg_a, gn_b = gb + dg_b;
        const float s_a  = al_a * da,  s_b  = al_b * db;
        sm.dg[pa][i] = dg_a;       sm.dg[pb][i] = dg_b;
        sm.sH[pa][it][i] = s_a;    sm.sH[pb][it][i] = s_b;
        __syncthreads();                                   // S2

        // ===== history dots: warp r handles slot j = r for all 4 problems =====
        if (r < it) {
            #pragma unroll
            for (int pp = 0; pp < P; pp++) {
                float4 dv = reinterpret_cast<const float4*>(sm.dg[pp])[c];
                float4 sv = reinterpret_cast<const float4*>(sm.sH[pp][r])[c];
                float4 yv = reinterpret_cast<const float4*>(sm.yH[pp][r])[c];
                float sp = sv.x*dv.x + sv.y*dv.y + sv.z*dv.z + sv.w*dv.w;
                float ep = yv.x*dv.x + yv.y*dv.y + yv.z*dv.z + yv.w*dv.w;
                sp = warp_sum(sp); ep = warp_sum(ep);
                if (c == 0) { sm.sig[pp][r] = sp; sm.eta[pp][r] = ep; }
            }
        }
        float u_a = dg_a, u_b = dg_b;        // H0*dg when identity
        if (!identity) {
            u_a = rowdot(Hinit + (size_t)i * N, sm.dg[pa]);
            u_b = rowdot(Hinit + (size_t)i * N, sm.dg[pb]);
        }
        __syncthreads();                                   // S3

        // ===== Hy via low-rank combination; commit; reduce ihdg/err2 =====
        float hya = u_a, hyb = u_b;
        #pragma unroll
        for (int j = 0; j < MAXIT; ++j) {
            if (j < it) {
                float c1a = sm.c1a[pa][j], bva = sm.bva[pa][j];
                float sga = sm.sig[pa][j], eta = sm.eta[pa][j];
                hya += (c1a * sga - bva * eta) * sm.sH[pa][j][i]
                     - (bva * sga)             * sm.yH[pa][j][i];
                float c1b = sm.c1a[pb][j], bvb = sm.bva[pb][j];
                float sgb = sm.sig[pb][j], etb = sm.eta[pb][j];
                hyb += (c1b * sgb - bvb * etb) * sm.sH[pb][j][i]
                     - (bvb * sgb)             * sm.yH[pb][j][i];
            }
        }
        const float gca = ma ? gn_a : ga;
        const float gcb = mb ? gn_b : gb;
        xa = ma ? xa + s_a : xa;
        xb = mb ? xb + s_b : xb;
        ga = gca; gb = gcb;
        {
            float ia = dg_a * hya, ib = dg_b * hyb;
            float ea = gca * gca,  eb = gcb * gcb;
            float v0 = (half == 0) ? ia : 0.f;
            float v1 = (half == 1) ? ia : 0.f;
            float v2 = (half == 0) ? ib : 0.f;
            float v3 = (half == 1) ? ib : 0.f;
            float w0 = (half == 0) ? ea : 0.f;
            float w1 = (half == 1) ? ea : 0.f;
            float w2 = (half == 0) ? eb : 0.f;
            float w3 = (half == 1) ? eb : 0.f;
            v0 = warp_sum(v0); v1 = warp_sum(v1); v2 = warp_sum(v2); v3 = warp_sum(v3);
            w0 = warp_sum(w0); w1 = warp_sum(w1); w2 = warp_sum(w2); w3 = warp_sum(w3);
            if (c == 0) {
                sm.redB[0 * 8 + r] = v0;  sm.redB[1 * 8 + r] = v1;
                sm.redB[2 * 8 + r] = v2;  sm.redB[3 * 8 + r] = v3;
                sm.redB[4 * 8 + r] = w0;  sm.redB[5 * 8 + r] = w1;
                sm.redB[6 * 8 + r] = w2;  sm.redB[7 * 8 + r] = w3;
            }
        }
        __syncthreads();                                   // S4
        const float ih_a = red_final(sm.redB, pa);
        const float ih_b = red_final(sm.redB, pb);
        const float e2_a = red_final(sm.redB, 4 + pa);
        const float e2_b = red_final(sm.redB, 4 + pb);

        const float biv_a = (sdg_a != 0.f) ? 1.f / sdg_a : 0.f;
        const float c1_a  = (sdg_a != 0.f) ? (sdg_a + ih_a) * biv_a * biv_a : 0.f;
        const float biv_b = (sdg_b != 0.f) ? 1.f / sdg_b : 0.f;
        const float c1_b  = (sdg_b != 0.f) ? (sdg_b + ih_b) * biv_b * biv_b : 0.f;

        // d_next = -H_new g_new via scalar recurrence (per owner problem)
        {
            const float mfa  = ma ? 1.f : 0.f;
            const float sgn  = al_a * gd_a + mfa * sdg_a;
            const float hygn = mfa * ih_a - al_a * dqd_a;
            const float cs   = biv_a * hygn - c1_a * sgn;
            const float ch   = biv_a * sgn - mfa;
            da = da + cs * s_a + ch * hya;
            sm.d[pa][i] = da;
            sm.yH[pa][it][i] = hya;
        }
        {
            const float mfb  = mb ? 1.f : 0.f;
            const float sgn  = al_b * gd_b + mfb * sdg_b;
            const float hygn = mfb * ih_b - al_b * dqd_b;
            const float cs   = biv_b * hygn - c1_b * sgn;
            const float ch   = biv_b * sgn - mfb;
            db = db + cs * s_b + ch * hyb;
            sm.d[pb][i] = db;
            sm.yH[pb][it][i] = hyb;
        }
        if (i == 0) {
            sm.c1a[pa][it] = c1_a; sm.bva[pa][it] = biv_a;
            sm.c1a[pb][it] = c1_b; sm.bva[pb][it] = biv_b;
        }
        ma = ma && (e2_a > 1e-12f);
        mb = mb && (e2_b > 1e-12f);
        __syncthreads();                                   // S5
    }

    out[gpa * N + i] = xa;
    out[gpb * N + i] = xb;
}

extern "C" void kernel_launch(void* const* d_in, const int* in_sizes, int n_in,
                              void* d_out, int out_size)
{
    const float* Hinit = (const float*)d_in[0];
    const float* Q     = (const float*)d_in[1];
    const float* bvec  = (const float*)d_in[2];
    const float* x0    = (const float*)d_in[3];
    float*       out   = (float*)d_out;

    const int nprob = out_size / N;    // B*E = 1024 (divisible by 4)
    const int smem  = (int)sizeof(SM);

    cudaFuncSetAttribute(bfgs_kernel, cudaFuncAttributeMaxDynamicSharedMemorySize, smem);
    check_hinit_kernel<<<1, 1024>>>(reinterpret_cast<const float4*>(Hinit));
    bfgs_kernel<<<nprob / P, 256, smem>>>(Hinit, Q, bvec, x0, out);
}

// round 14
// speedup vs baseline: 3.3857x; 1.0263x over previous
#include <cuda_runtime.h>

constexpr int N     = 128;
constexpr int MAXIT = 8;
constexpr int P     = 4;      // problems per CTA

// Dynamic-smem layout (P=4 problems per CTA)
struct SM {
    __align__(16) float d  [P][N];
    __align__(16) float dg [P][N];
    __align__(16) float sH [P][MAXIT][N];
    __align__(16) float yH [P][MAXIT][N];
    __align__(16) float qpA[P][8 * 128];   // matvec partials [prob][r][col]
    __align__(16) float sig[P][8];
    __align__(16) float eta[P][8];
    __align__(16) float c1a[P][8];
    __align__(16) float bva[P][8];
    __align__(16) float redGd[P * 4];      // gd[p]  : 4 warps of that half
    __align__(16) float redDq[P * 8];      // dqd[p] : all 8 warps
    __align__(16) float redU [P * 4];      // udg[p] : 4 warps of that half
    __align__(16) float redE [P * 4];      // err2[p]: 4 warps of that half
};

__device__ __forceinline__ float warp_sum(float v) {
    #pragma unroll
    for (int o = 16; o > 0; o >>= 1) v += __shfl_xor_sync(0xffffffffu, v, o);
    return v;
}

__device__ __forceinline__ float sum4(const float* red) {
    float4 a = *reinterpret_cast<const float4*>(red);
    return (a.x + a.y) + (a.z + a.w);
}
__device__ __forceinline__ float sum8(const float* red) {
    const float4* r4 = reinterpret_cast<const float4*>(red);
    float4 a = r4[0], b = r4[1];
    return (a.x + a.y) + (a.z + a.w) + (b.x + b.y) + (b.z + b.w);
}

__device__ __forceinline__ float combine8(const float* qpA, int i) {
    float s = 0.f;
    #pragma unroll
    for (int r = 0; r < 8; r++) s += qpA[r * 128 + i];
    return s;
}

// general-path row dot for arbitrary Hinit
__device__ __forceinline__ float rowdot(const float* __restrict__ Hrow,
                                        const float* v) {
    const float4* h4 = reinterpret_cast<const float4*>(Hrow);
    const float4* v4 = reinterpret_cast<const float4*>(v);
    float acc = 0.f;
    #pragma unroll 8
    for (int k = 0; k < 32; k++) {
        float4 hh = h4[k], vv = v4[k];
        acc += hh.x * vv.x + hh.y * vv.y + hh.z * vv.z + hh.w * vv.w;
    }
    return acc;
}

__global__ __launch_bounds__(256, 3)
void bfgs_kernel(const float* __restrict__ Hinit,
                 const float* __restrict__ Q,
                 const float* __restrict__ bvec,
                 const float* __restrict__ x0,
                 float* __restrict__ out)
{
    extern __shared__ char smraw[];
    SM& sm = *reinterpret_cast<SM*>(smraw);

    const int t    = threadIdx.x;
    const int i    = t & 127;          // owned element
    const int half = t >> 7;           // owner probs: half and half+2
    const int c    = t & 31;           // matvec: column group (4c..4c+3)
    const int r    = t >> 5;           // matvec: k-range / history slot (warp id)
    const int rr   = r & 3;            // warp index within its half
    const int pa   = half;
    const int pb   = half + 2;
    const int gpa  = P * blockIdx.x + pa;
    const int gpb  = P * blockIdx.x + pb;

    // ---- per-CTA identity check on Hinit (16 float4 LDG/thread, L2-shared);
    //      the __syncthreads_and doubles as the x0-staging barrier ----
    float xa = x0[gpa * N + i], xb = x0[gpb * N + i];
    sm.d[pa][i] = xa;  sm.d[pb][i] = xb;
    int ok = 1;
    {
        const float4* H4 = reinterpret_cast<const float4*>(Hinit);
        #pragma unroll 4
        for (int idx = t; idx < 4096; idx += 256) {
            const int base = idx * 4;
            const int row  = base >> 7;
            const int col  = base & 127;
            float4 v = H4[idx];
            ok &= (v.x == ((row == col + 0) ? 1.f : 0.f));
            ok &= (v.y == ((row == col + 1) ? 1.f : 0.f));
            ok &= (v.z == ((row == col + 2) ? 1.f : 0.f));
            ok &= (v.w == ((row == col + 3) ? 1.f : 0.f));
        }
    }
    const int identity = __syncthreads_and(ok);   // also publishes sm.d

    // ---- matvec: partials for all 4 problems sharing each Q load ----
    auto qmv4 = [&](float4& A0, float4& A1, float4& A2, float4& A3) {
        const float4* qr4 = reinterpret_cast<const float4*>(Q + (size_t)(16 * r) * N) + c;
        const float4* k0 = reinterpret_cast<const float4*>(sm.d[0] + 16 * r);
        const float4* k1 = reinterpret_cast<const float4*>(sm.d[1] + 16 * r);
        const float4* k2 = reinterpret_cast<const float4*>(sm.d[2] + 16 * r);
        const float4* k3 = reinterpret_cast<const float4*>(sm.d[3] + 16 * r);
        A0 = make_float4(0.f, 0.f, 0.f, 0.f); A1 = A0; A2 = A0; A3 = A0;
        #pragma unroll 1
        for (int jj = 0; jj < 4; jj++) {
            float4 q0 = qr4[(4 * jj + 0) * 32];
            float4 q1 = qr4[(4 * jj + 1) * 32];
            float4 q2 = qr4[(4 * jj + 2) * 32];
            float4 q3 = qr4[(4 * jj + 3) * 32];
            float4 u;
            u = k0[jj];
            A0.x += q0.x*u.x + q1.x*u.y + q2.x*u.z + q3.x*u.w;
            A0.y += q0.y*u.x + q1.y*u.y + q2.y*u.z + q3.y*u.w;
            A0.z += q0.z*u.x + q1.z*u.y + q2.z*u.z + q3.z*u.w;
            A0.w += q0.w*u.x + q1.w*u.y + q2.w*u.z + q3.w*u.w;
            u = k1[jj];
            A1.x += q0.x*u.x + q1.x*u.y + q2.x*u.z + q3.x*u.w;
            A1.y += q0.y*u.x + q1.y*u.y + q2.y*u.z + q3.y*u.w;
            A1.z += q0.z*u.x + q1.z*u.y + q2.z*u.z + q3.z*u.w;
            A1.w += q0.w*u.x + q1.w*u.y + q2.w*u.z + q3.w*u.w;
            u = k2[jj];
            A2.x += q0.x*u.x + q1.x*u.y + q2.x*u.z + q3.x*u.w;
            A2.y += q0.y*u.x + q1.y*u.y + q2.y*u.z + q3.y*u.w;
            A2.z += q0.z*u.x + q1.z*u.y + q2.z*u.z + q3.z*u.w;
            A2.w += q0.w*u.x + q1.w*u.y + q2.w*u.z + q3.w*u.w;
            u = k3[jj];
            A3.x += q0.x*u.x + q1.x*u.y + q2.x*u.z + q3.x*u.w;
            A3.y += q0.y*u.x + q1.y*u.y + q2.y*u.z + q3.y*u.w;
            A3.z += q0.z*u.x + q1.z*u.y + q2.z*u.z + q3.z*u.w;
            A3.w += q0.w*u.x + q1.w*u.y + q2.w*u.z + q3.w*u.w;
        }
    };
    auto store_parts = [&](float4 A0, float4 A1, float4 A2, float4 A3) {
        reinterpret_cast<float4*>(sm.qpA[0])[t] = A0;
        reinterpret_cast<float4*>(sm.qpA[1])[t] = A1;
        reinterpret_cast<float4*>(sm.qpA[2])[t] = A2;
        reinterpret_cast<float4*>(sm.qpA[3])[t] = A3;
    };

    // ---- g0 = Q x0 - b ----
    {
        float4 A0, A1, A2, A3;
        qmv4(A0, A1, A2, A3);
        store_parts(A0, A1, A2, A3);
    }
    __syncthreads();
    float ga = combine8(sm.qpA[pa], i) - bvec[gpa * N + i];
    float gb = combine8(sm.qpA[pb], i) - bvec[gpb * N + i];

    // ---- d0 = -H0 g0 ----
    float da, db;
    if (identity) {
        da = -ga; db = -gb;
        sm.d[pa][i] = da; sm.d[pb][i] = db;
        __syncthreads();
    } else {
        sm.dg[pa][i] = ga; sm.dg[pb][i] = gb;
        __syncthreads();
        da = -rowdot(Hinit + (size_t)i * N, sm.dg[pa]);
        db = -rowdot(Hinit + (size_t)i * N, sm.dg[pb]);
        sm.d[pa][i] = da; sm.d[pb][i] = db;
        __syncthreads();
    }

    bool ma = true, mb = true;    // per-owner-problem updating flags

    #pragma unroll 1
    for (int it = 0; it < MAXIT; ++it) {
        // ===== Phase A: qd = Q d (4 problems); gd, dQd =====
        float4 A0, A1, A2, A3;
        qmv4(A0, A1, A2, A3);
        store_parts(A0, A1, A2, A3);
        {
            float4 u0 = reinterpret_cast<const float4*>(sm.d[0])[c];
            float4 u1 = reinterpret_cast<const float4*>(sm.d[1])[c];
            float4 u2 = reinterpret_cast<const float4*>(sm.d[2])[c];
            float4 u3 = reinterpret_cast<const float4*>(sm.d[3])[c];
            float dq0 = A0.x*u0.x + A0.y*u0.y + A0.z*u0.z + A0.w*u0.w;
            float dq1 = A1.x*u1.x + A1.y*u1.y + A1.z*u1.z + A1.w*u1.w;
            float dq2 = A2.x*u2.x + A2.y*u2.y + A2.z*u2.z + A2.w*u2.w;
            float dq3 = A3.x*u3.x + A3.y*u3.y + A3.z*u3.z + A3.w*u3.w;
            float gdA = warp_sum(ga * da);     // warp is half-uniform: no masking
            float gdB = warp_sum(gb * db);
            dq0 = warp_sum(dq0); dq1 = warp_sum(dq1);
            dq2 = warp_sum(dq2); dq3 = warp_sum(dq3);
            if (c == 0) {
                sm.redGd[pa * 4 + rr] = gdA;
                sm.redGd[pb * 4 + rr] = gdB;
                sm.redDq[0 * 8 + r] = dq0; sm.redDq[1 * 8 + r] = dq1;
                sm.redDq[2 * 8 + r] = dq2; sm.redDq[3 * 8 + r] = dq3;
            }
        }
        __syncthreads();                                   // S1
        const float gd_a  = sum4(sm.redGd + pa * 4);
        const float gd_b  = sum4(sm.redGd + pb * 4);
        const float dqd_a = sum8(sm.redDq + pa * 8);
        const float dqd_b = sum8(sm.redDq + pb * 8);

        const float al_a = -gd_a / fmaxf(dqd_a, 1e-12f);
        const float al_b = -gd_b / fmaxf(dqd_b, 1e-12f);
        const float sdg_a = al_a * al_a * dqd_a;
        const float sdg_b = al_b * al_b * dqd_b;

        const float dg_a = al_a * combine8(sm.qpA[pa], i);
        const float dg_b = al_b * combine8(sm.qpA[pb], i);
        const float s_a  = al_a * da,  s_b  = al_b * db;
        sm.dg[pa][i] = dg_a;       sm.dg[pb][i] = dg_b;
        sm.sH[pa][it][i] = s_a;    sm.sH[pb][it][i] = s_b;
        __syncthreads();                                   // S2

        // ===== W3: history dots + owner reductions (udg, err2) =====
        if (r < it) {
            #pragma unroll
            for (int pp = 0; pp < P; pp++) {
                float4 dv = reinterpret_cast<const float4*>(sm.dg[pp])[c];
                float4 sv = reinterpret_cast<const float4*>(sm.sH[pp][r])[c];
                float4 yv = reinterpret_cast<const float4*>(sm.yH[pp][r])[c];
                float sp = sv.x*dv.x + sv.y*dv.y + sv.z*dv.z + sv.w*dv.w;
                float ep = yv.x*dv.x + yv.y*dv.y + yv.z*dv.z + yv.w*dv.w;
                sp = warp_sum(sp); ep = warp_sum(ep);
                if (c == 0) { sm.sig[pp][r] = sp; sm.eta[pp][r] = ep; }
            }
        }
        // base u = H0*dg and its dot with dg (exact dg.H0.dg)
        float u_a = dg_a, u_b = dg_b;
        if (!identity) {
            u_a = rowdot(Hinit + (size_t)i * N, sm.dg[pa]);
            u_b = rowdot(Hinit + (size_t)i * N, sm.dg[pb]);
        }
        // commit x,g with OLD mask; exact err2 on committed g
        const float gca = ma ? ga + dg_a : ga;
        const float gcb = mb ? gb + dg_b : gb;
        xa = ma ? xa + s_a : xa;
        xb = mb ? xb + s_b : xb;
        ga = gca; gb = gcb;
        {
            float uA = warp_sum(dg_a * u_a);
            float uB = warp_sum(dg_b * u_b);
            float eA = warp_sum(gca * gca);
            float eB = warp_sum(gcb * gcb);
            if (c == 0) {
                sm.redU[pa * 4 + rr] = uA;  sm.redU[pb * 4 + rr] = uB;
                sm.redE[pa * 4 + rr] = eA;  sm.redE[pb * 4 + rr] = eB;
            }
        }
        __syncthreads();                                   // S3
        const float udg_a = sum4(sm.redU + pa * 4);
        const float udg_b = sum4(sm.redU + pb * 4);
        const float e2_a  = sum4(sm.redE + pa * 4);
        const float e2_b  = sum4(sm.redE + pb * 4);

        // ===== hy (low-rank) and ihdg (scalar) in one merged loop =====
        float hya = u_a, hyb = u_b;
        float ih_a = udg_a, ih_b = udg_b;
        #pragma unroll
        for (int j = 0; j < MAXIT; ++j) {
            if (j < it) {
                const float c1j = sm.c1a[pa][j], bj = sm.bva[pa][j];
                const float sg  = sm.sig[pa][j], et = sm.eta[pa][j];
                const float wj  = c1j * sg - bj * et;
                const float vj  = -bj * sg;
                hya  += wj * sm.sH[pa][j][i] + vj * sm.yH[pa][j][i];
                ih_a += sg * wj + et * vj;
                const float c1k = sm.c1a[pb][j], bk = sm.bva[pb][j];
                const float sh  = sm.sig[pb][j], eu = sm.eta[pb][j];
                const float wk  = c1k * sh - bk * eu;
                const float vk  = -bk * sh;
                hyb  += wk * sm.sH[pb][j][i] + vk * sm.yH[pb][j][i];
                ih_b += sh * wk + eu * vk;
            }
        }

        const float biv_a = (sdg_a != 0.f) ? 1.f / sdg_a : 0.f;
        const float c1_a  = (sdg_a != 0.f) ? (sdg_a + ih_a) * biv_a * biv_a : 0.f;
        const float biv_b = (sdg_b != 0.f) ? 1.f / sdg_b : 0.f;
        const float c1_b  = (sdg_b != 0.f) ? (sdg_b + ih_b) * biv_b * biv_b : 0.f;

        // ===== d_next = -H_new g_new via scalar recurrence =====
        {
            const float mf   = ma ? 1.f : 0.f;
            const float sgn  = al_a * gd_a + mf * sdg_a;   // s . g_committed
            const float hygn = mf * ih_a - al_a * dqd_a;   // Hy . g_committed
            const float cs   = biv_a * hygn - c1_a * sgn;
            const float ch   = biv_a * sgn - mf;
            da = da + cs * s_a + ch * hya;
            sm.d[pa][i] = da;
            sm.yH[pa][it][i] = hya;
        }
        {
            const float mf   = mb ? 1.f : 0.f;
            const float sgn  = al_b * gd_b + mf * sdg_b;
            const float hygn = mf * ih_b - al_b * dqd_b;
            const float cs   = biv_b * hygn - c1_b * sgn;
            const float ch   = biv_b * sgn - mf;
            db = db + cs * s_b + ch * hyb;
            sm.d[pb][i] = db;
            sm.yH[pb][it][i] = hyb;
        }
        if (i == 0) {
            sm.c1a[pa][it] = c1_a; sm.bva[pa][it] = biv_a;
            sm.c1a[pb][it] = c1_b; sm.bva[pb][it] = biv_b;
        }
        ma = ma && (e2_a > 1e-12f);    // err > 1e-6  <=>  err^2 > 1e-12
        mb = mb && (e2_b > 1e-12f);
        __syncthreads();                                   // S4
    }

    out[gpa * N + i] = xa;
    out[gpb * N + i] = xb;
}

extern "C" void kernel_launch(void* const* d_in, const int* in_sizes, int n_in,
                              void* d_out, int out_size)
{
    const float* Hinit = (const float*)d_in[0];
    const float* Q     = (const float*)d_in[1];
    const float* bvec  = (const float*)d_in[2];
    const float* x0    = (const float*)d_in[3];
    float*       out   = (float*)d_out;

    const int nprob = out_size / N;    // B*E = 1024 (divisible by 4)
    const int smem  = (int)sizeof(SM);

    cudaFuncSetAttribute(bfgs_kernel, cudaFuncAttributeMaxDynamicSharedMemorySize, smem);
    bfgs_kernel<<<nprob / P, 256, smem>>>(Hinit, Q, bvec, x0, out);
}